// round 8
// baseline (speedup 1.0000x reference)
#include <cuda_runtime.h>
#include <cuda_fp16.h>
#include <math.h>
#include <stdint.h>

#define B_ 4
#define S_ 2048
#define D_ 1024
#define H_ 16
#define HD_ 64
#define M_ (B_*S_)   // 8192

// fp16 scratch
__device__ __half g_qh[(size_t)B_*H_*S_*HD_];
__device__ __half g_kh[(size_t)B_*H_*S_*HD_];
__device__ __half g_vh[(size_t)B_*H_*S_*HD_];
__device__ __half g_xh[(size_t)M_*D_];
__device__ __half g_wvh[(size_t)M_*D_];
__device__ __half g_wt[(size_t)3*H_*HD_*D_];    // [z][h][n=64][k=1024]
__device__ __half g_woh[(size_t)D_*D_];         // [n][k]

// ---------------------------------------------------------------------------
__device__ __forceinline__ uint32_t smem_u32(const void* p) {
    uint32_t a;
    asm("{ .reg .u64 t; cvta.to.shared.u64 t, %1; cvt.u32.u64 %0, t; }" : "=r"(a) : "l"(p));
    return a;
}
__device__ __forceinline__ void cpa16(uint32_t dst, const void* src) {
    asm volatile("cp.async.cg.shared.global [%0], [%1], 16;" :: "r"(dst), "l"(src));
}
__device__ __forceinline__ void cpa_commit() {
    asm volatile("cp.async.commit_group;" ::: "memory");
}
__device__ __forceinline__ float ex2(float x) {
    float r; asm("ex2.approx.ftz.f32 %0, %1;" : "=f"(r) : "f"(x)); return r;
}
__device__ __forceinline__ void mma16816(float c[4], const uint32_t a[4], const uint32_t b[2]) {
    asm volatile("mma.sync.aligned.m16n8k16.row.col.f32.f16.f16.f32 "
                 "{%0,%1,%2,%3}, {%4,%5,%6,%7}, {%8,%9}, {%0,%1,%2,%3};"
                 : "+f"(c[0]), "+f"(c[1]), "+f"(c[2]), "+f"(c[3])
                 : "r"(a[0]), "r"(a[1]), "r"(a[2]), "r"(a[3]), "r"(b[0]), "r"(b[1]));
}

// ============ GEMM: CTA 128x256, warp 64x64, BK=64, 3-stage ring ===========
#define RS2 144
#define TILE2 (128 * RS2)          // A tile: 18432 B
#define BT2   (256 * RS2)          // B tile: 36864 B
#define STG3  (TILE2 + BT2)        // 55296 B per stage
#define GSMEM (3 * STG3)           // 165888 B
#define NKT2 16                    // 1024 / 64

__device__ __forceinline__ void load_stage(uint32_t sbase,
                                           const __half* __restrict__ A,
                                           const __half* __restrict__ Bg,
                                           int kt, int tid) {
    const uint32_t sA = sbase, sB = sbase + TILE2;
    #pragma unroll
    for (int i = 0; i < 12; ++i) {
        int idx = tid + i * 256;           // 0..3071
        int row = idx >> 3, c = idx & 7;
        if (i < 4) {                       // rows 0..127 -> A
            cpa16(sA + row * RS2 + c * 16, A + (size_t)row * D_ + kt * 64 + c * 8);
        } else {                           // rows 128..383 -> B rows 0..255
            int r = row - 128;
            cpa16(sB + r * RS2 + c * 16, Bg + (size_t)r * D_ + kt * 64 + c * 8);
        }
    }
}

// fragments for one k16 step: A 64x16 (this warp's rows), B 64x16 (this warp's cols)
__device__ __forceinline__ void load_frags(uint32_t sA, uint32_t sB, int ks,
                                           int warp_m, int warp_n, int lane,
                                           uint32_t a[4][4], uint32_t b[8][2]) {
    #pragma unroll
    for (int i = 0; i < 4; ++i) {
        int row = warp_m * 64 + i * 16 + (lane & 15);
        uint32_t addr = sA + row * RS2 + (ks * 16 + (lane >> 4) * 8) * 2;
        asm volatile("ldmatrix.sync.aligned.m8n8.x4.shared.b16 {%0,%1,%2,%3}, [%4];"
                     : "=r"(a[i][0]), "=r"(a[i][1]), "=r"(a[i][2]), "=r"(a[i][3])
                     : "r"(addr));
    }
    #pragma unroll
    for (int jj = 0; jj < 4; ++jj) {
        int g = lane >> 3, lr = lane & 7;
        int n = warp_n * 64 + jj * 16 + (g >> 1) * 8 + lr;
        uint32_t addr = sB + n * RS2 + (ks * 16 + (g & 1) * 8) * 2;
        uint32_t r0, r1, r2, r3;
        asm volatile("ldmatrix.sync.aligned.m8n8.x4.shared.b16 {%0,%1,%2,%3}, [%4];"
                     : "=r"(r0), "=r"(r1), "=r"(r2), "=r"(r3) : "r"(addr));
        b[jj * 2][0] = r0; b[jj * 2][1] = r1;
        b[jj * 2 + 1][0] = r2; b[jj * 2 + 1][1] = r3;
    }
}

__device__ __forceinline__ void do_mmas(const uint32_t a[4][4], const uint32_t b[8][2],
                                        float c[4][8][4]) {
    #pragma unroll
    for (int i = 0; i < 4; ++i)
        #pragma unroll
        for (int j = 0; j < 8; ++j)
            mma16816(c[i][j], a[i], b[j]);
}

__device__ __forceinline__ void gemm_main(uint32_t s, const __half* __restrict__ A,
                                          const __half* __restrict__ Bg,
                                          int tid, int warp_m, int warp_n, int lane,
                                          float c[4][8][4]) {
    load_stage(s + 0 * STG3, A, Bg, 0, tid); cpa_commit();
    load_stage(s + 1 * STG3, A, Bg, 1, tid); cpa_commit();

    uint32_t af[2][4][4], bf[2][8][2];

    #pragma unroll 1
    for (int kt = 0; kt < NKT2; ++kt) {
        if (kt < NKT2 - 1) asm volatile("cp.async.wait_group 1;" ::: "memory");
        else               asm volatile("cp.async.wait_group 0;" ::: "memory");
        __syncthreads();
        if (kt + 2 < NKT2) {
            load_stage(s + ((kt + 2) % 3) * STG3, A, Bg, kt + 2, tid);
            cpa_commit();
        }
        const uint32_t sA = s + (kt % 3) * STG3, sB = sA + TILE2;

        load_frags(sA, sB, 0, warp_m, warp_n, lane, af[0], bf[0]);
        #pragma unroll
        for (int ks = 0; ks < 4; ++ks) {
            if (ks < 3)
                load_frags(sA, sB, ks + 1, warp_m, warp_n, lane,
                           af[(ks + 1) & 1], bf[(ks + 1) & 1]);
            do_mmas(af[ks & 1], bf[ks & 1], c);
        }
    }
}

// ---------------------------------------------------------------------------
// QKV projection -> fp16 Q/K/V. Per block: 128 rows x 4 heads (N=256).
// ---------------------------------------------------------------------------
__global__ __launch_bounds__(256, 1) void qkv_mma(
    const __half* __restrict__ Xh, const __half* __restrict__ Wt,
    const float* __restrict__ bq, const float* __restrict__ bk,
    const float* __restrict__ bv) {
    extern __shared__ __align__(16) char sm[];
    const uint32_t s = smem_u32(sm);
    const int tid = threadIdx.x, lane = tid & 31, wid = tid >> 5;
    const int warp_m = wid & 1, warp_n = wid >> 1;
    const int z = blockIdx.z, h0 = blockIdx.x * 4, m0 = blockIdx.y * 128;

    const __half* A  = Xh + (size_t)m0 * D_;
    const __half* Bg = Wt + ((size_t)(z * H_ + h0) * HD_) * D_;
    const float* bias = (z == 0) ? bq : (z == 1) ? bk : bv;
    __half* out       = (z == 0) ? g_qh : (z == 1) ? g_kh : g_vh;

    float c[4][8][4] = {};
    gemm_main(s, A, Bg, tid, warp_m, warp_n, lane, c);

    #pragma unroll
    for (int i = 0; i < 4; ++i) {
        #pragma unroll
        for (int j = 0; j < 8; ++j) {
            const int n = warp_n * 64 + j * 8 + (lane & 3) * 2;   // 0..255
            const int head = h0 + (n >> 6), e = n & 63;
            const float b0 = bias[head * HD_ + e], b1 = bias[head * HD_ + e + 1];
            #pragma unroll
            for (int half_ = 0; half_ < 2; ++half_) {
                const int m = m0 + warp_m * 64 + i * 16 + (lane >> 2) + half_ * 8;
                const int bb = m >> 11, sI = m & 2047;
                __half2 hv = __floats2half2_rn(c[i][j][half_ * 2 + 0] + b0,
                                               c[i][j][half_ * 2 + 1] + b1);
                *(__half2*)(out + (((size_t)(bb * H_ + head) * S_ + sI) * HD_ + e)) = hv;
            }
        }
    }
}

// ---------------------------------------------------------------------------
// Output projection: C = WVh * Woh^T + bo. Per block: 128 rows x 256 cols.
// ---------------------------------------------------------------------------
__global__ __launch_bounds__(256, 1) void out_mma(
    const __half* __restrict__ WVh, const __half* __restrict__ Woh,
    const float* __restrict__ bo, float* __restrict__ outp) {
    extern __shared__ __align__(16) char sm[];
    const uint32_t s = smem_u32(sm);
    const int tid = threadIdx.x, lane = tid & 31, wid = tid >> 5;
    const int warp_m = wid & 1, warp_n = wid >> 1;
    const int n0 = blockIdx.x * 256, m0 = blockIdx.y * 128;

    const __half* A  = WVh + (size_t)m0 * D_;
    const __half* Bg = Woh + (size_t)n0 * D_;

    float c[4][8][4] = {};
    gemm_main(s, A, Bg, tid, warp_m, warp_n, lane, c);

    #pragma unroll
    for (int i = 0; i < 4; ++i) {
        #pragma unroll
        for (int j = 0; j < 8; ++j) {
            const int n = n0 + warp_n * 64 + j * 8 + (lane & 3) * 2;
            const float b0 = bo[n], b1 = bo[n + 1];
            #pragma unroll
            for (int half_ = 0; half_ < 2; ++half_) {
                const int m = m0 + warp_m * 64 + i * 16 + (lane >> 2) + half_ * 8;
                float2 v;
                v.x = c[i][j][half_ * 2 + 0] + b0;
                v.y = c[i][j][half_ * 2 + 1] + b1;
                *(float2*)(outp + (size_t)m * D_ + n) = v;
            }
        }
    }
}

// =================== attention (unchanged, validated) =======================
#define ARS 144
#define ATILE (64 * ARS)
#define ASTG (2 * ATILE)
#define ASMEM (3 * ASTG)           // 55296 B

__global__ __launch_bounds__(256) void attn_mma() {
    extern __shared__ __align__(16) char sm[];
    const uint32_t s = smem_u32(sm);
    const int tid = threadIdx.x, lane = tid & 31, w = tid >> 5;
    const int bh = blockIdx.y, q0 = blockIdx.x * 128;

    const __half* __restrict__ Qb = g_qh + (size_t)bh * S_ * HD_;
    const __half* __restrict__ Kb = g_kh + (size_t)bh * S_ * HD_;
    const __half* __restrict__ Vb = g_vh + (size_t)bh * S_ * HD_;

    const int r0 = q0 + w * 16 + (lane >> 2);
    const int cq = lane & 3;
    uint32_t qf[4][4];
    {
        const __half2* Qr0 = (const __half2*)(Qb + (size_t)r0 * HD_);
        const __half2* Qr1 = (const __half2*)(Qb + (size_t)(r0 + 8) * HD_);
        #pragma unroll
        for (int t = 0; t < 4; ++t) {
            qf[t][0] = *(const uint32_t*)&Qr0[t * 8 + cq];
            qf[t][1] = *(const uint32_t*)&Qr1[t * 8 + cq];
            qf[t][2] = *(const uint32_t*)&Qr0[t * 8 + 4 + cq];
            qf[t][3] = *(const uint32_t*)&Qr1[t * 8 + 4 + cq];
        }
    }

    float o[8][4];
    #pragma unroll
    for (int j = 0; j < 8; ++j)
        #pragma unroll
        for (int x = 0; x < 4; ++x) o[j][x] = 0.f;
    float m0 = -INFINITY, m1 = -INFINITY, l0 = 0.f, l1 = 0.f;

    const int NT = (q0 + 128) / 64;
    const float SC = 0.18033688f;

    auto load_tile = [&](int kt, int stg) {
        const uint32_t base = s + stg * ASTG;
        #pragma unroll
        for (int i = 0; i < 2; ++i) {
            int idx = tid + i * 256;
            int row = idx >> 3, c = idx & 7;
            const size_t go = (size_t)(kt * 64 + row) * HD_ + c * 8;
            cpa16(base + row * ARS + c * 16, Kb + go);
            cpa16(base + ATILE + row * ARS + c * 16, Vb + go);
        }
    };

    load_tile(0, 0); cpa_commit();
    if (NT > 1) { load_tile(1, 1); cpa_commit(); }

    const uint32_t kb_lane = (lane & 7) * ARS + ((lane >> 3) & 1) * 16;
    const uint32_t vb_lane = (lane & 15) * ARS;

    #pragma unroll 1
    for (int kt = 0; kt < NT; ++kt) {
        const int k0 = kt * 64;
        if (kt < NT - 1) asm volatile("cp.async.wait_group 1;" ::: "memory");
        else             asm volatile("cp.async.wait_group 0;" ::: "memory");
        __syncthreads();
        if (kt + 2 < NT) { load_tile(kt + 2, (kt + 2) % 3); cpa_commit(); }

        const uint32_t sK = s + (kt % 3) * ASTG, sV = sK + ATILE;

        float sa[8][4];
        #pragma unroll
        for (int j = 0; j < 8; ++j)
            #pragma unroll
            for (int x = 0; x < 4; ++x) sa[j][x] = 0.f;
        #pragma unroll
        for (int t = 0; t < 4; ++t) {
            #pragma unroll
            for (int j = 0; j < 8; ++j) {
                uint32_t b[2];
                uint32_t addr = sK + kb_lane + j * 8 * ARS + t * 32;
                asm volatile("ldmatrix.sync.aligned.m8n8.x2.shared.b16 {%0,%1}, [%2];"
                             : "=r"(b[0]), "=r"(b[1]) : "r"(addr));
                mma16816(sa[j], qf[t], b);
            }
        }

        const bool needmask = (k0 + 63 > r0);
        float tm0 = -INFINITY, tm1 = -INFINITY;
        #pragma unroll
        for (int j = 0; j < 8; ++j) {
            float v0 = sa[j][0] * SC, v1 = sa[j][1] * SC;
            float v2 = sa[j][2] * SC, v3 = sa[j][3] * SC;
            if (needmask) {
                const int col = k0 + j * 8 + (lane & 3) * 2;
                if (col > r0)         v0 = -INFINITY;
                if (col + 1 > r0)     v1 = -INFINITY;
                if (col > r0 + 8)     v2 = -INFINITY;
                if (col + 1 > r0 + 8) v3 = -INFINITY;
            }
            sa[j][0] = v0; sa[j][1] = v1; sa[j][2] = v2; sa[j][3] = v3;
            tm0 = fmaxf(tm0, fmaxf(v0, v1));
            tm1 = fmaxf(tm1, fmaxf(v2, v3));
        }
        tm0 = fmaxf(tm0, __shfl_xor_sync(0xffffffffu, tm0, 1));
        tm0 = fmaxf(tm0, __shfl_xor_sync(0xffffffffu, tm0, 2));
        tm1 = fmaxf(tm1, __shfl_xor_sync(0xffffffffu, tm1, 1));
        tm1 = fmaxf(tm1, __shfl_xor_sync(0xffffffffu, tm1, 2));

        const float mn0 = fmaxf(m0, tm0), mn1 = fmaxf(m1, tm1);
        const float c0 = ex2(m0 - mn0), c1 = ex2(m1 - mn1);
        m0 = mn0; m1 = mn1;

        float ts0 = 0.f, ts1 = 0.f;
        uint32_t pa[4][4];
        #pragma unroll
        for (int j = 0; j < 8; ++j) {
            const float p0 = ex2(sa[j][0] - mn0), p1 = ex2(sa[j][1] - mn0);
            const float p2 = ex2(sa[j][2] - mn1), p3 = ex2(sa[j][3] - mn1);
            ts0 += p0 + p1; ts1 += p2 + p3;
            const __half2 h01 = __floats2half2_rn(p0, p1);
            const __half2 h23 = __floats2half2_rn(p2, p3);
            const int t = j >> 1;
            if ((j & 1) == 0) {
                pa[t][0] = *(const uint32_t*)&h01;
                pa[t][1] = *(const uint32_t*)&h23;
            } else {
                pa[t][2] = *(const uint32_t*)&h01;
                pa[t][3] = *(const uint32_t*)&h23;
            }
        }
        ts0 += __shfl_xor_sync(0xffffffffu, ts0, 1);
        ts0 += __shfl_xor_sync(0xffffffffu, ts0, 2);
        ts1 += __shfl_xor_sync(0xffffffffu, ts1, 1);
        ts1 += __shfl_xor_sync(0xffffffffu, ts1, 2);
        l0 = l0 * c0 + ts0;
        l1 = l1 * c1 + ts1;

        #pragma unroll
        for (int j = 0; j < 8; ++j) {
            o[j][0] *= c0; o[j][1] *= c0;
            o[j][2] *= c1; o[j][3] *= c1;
        }

        #pragma unroll
        for (int t = 0; t < 4; ++t) {
            #pragma unroll
            for (int j = 0; j < 8; ++j) {
                uint32_t b[2];
                uint32_t addr = sV + vb_lane + t * 16 * ARS + j * 16;
                asm volatile("ldmatrix.sync.aligned.m8n8.x2.trans.shared.b16 {%0,%1}, [%2];"
                             : "=r"(b[0]), "=r"(b[1]) : "r"(addr));
                mma16816(o[j], pa[t], b);
            }
        }
    }

    const float i0 = 1.f / l0, i1 = 1.f / l1;
    const int b = bh >> 4, h = bh & 15;
    __half* out0 = g_wvh + ((size_t)(b * S_) + r0) * D_ + h * HD_ + (lane & 3) * 2;
    __half* out1 = g_wvh + ((size_t)(b * S_) + r0 + 8) * D_ + h * HD_ + (lane & 3) * 2;
    #pragma unroll
    for (int j = 0; j < 8; ++j) {
        *(__half2*)(out0 + j * 8) = __floats2half2_rn(o[j][0] * i0, o[j][1] * i0);
        *(__half2*)(out1 + j * 8) = __floats2half2_rn(o[j][2] * i1, o[j][3] * i1);
    }
}

// ---------------------------------------------------------------------------
// converts + weight transpose
// ---------------------------------------------------------------------------
__global__ void cvt_f32_f16(const float* __restrict__ in, __half* __restrict__ out, int n) {
    int i = (blockIdx.x * blockDim.x + threadIdx.x) * 4;
    if (i < n) {
        float4 v = *(const float4*)(in + i);
        __half2* o = (__half2*)(out + i);
        o[0] = __floats2half2_rn(v.x, v.y);
        o[1] = __floats2half2_rn(v.z, v.w);
    }
}

__global__ void wtrans(const float* __restrict__ Wq, const float* __restrict__ Wk,
                       const float* __restrict__ Wv) {
    __shared__ float t[32][33];
    const int zh = blockIdx.z, z = zh >> 4, h = zh & 15;
    const float* W = ((z == 0) ? Wq : (z == 1) ? Wk : Wv) + (size_t)h * D_ * HD_;
    __half* out = g_wt + (size_t)zh * HD_ * D_;
    const int n0 = blockIdx.x * 32, k0 = blockIdx.y * 32;
    const int tx = threadIdx.x, ty = threadIdx.y;
    #pragma unroll
    for (int i = 0; i < 32; i += 8)
        t[ty + i][tx] = W[(size_t)(k0 + ty + i) * HD_ + n0 + tx];
    __syncthreads();
    #pragma unroll
    for (int i = 0; i < 32; i += 8)
        out[(size_t)(n0 + ty + i) * D_ + k0 + tx] = __float2half_rn(t[tx][ty + i]);
}

// ---------------------------------------------------------------------------
extern "C" void kernel_launch(void* const* d_in, const int* in_sizes, int n_in,
                              void* d_out, int out_size) {
    const float* X  = (const float*)d_in[0];
    const float* Wq = (const float*)d_in[1];
    const float* bq = (const float*)d_in[2];
    const float* Wk = (const float*)d_in[3];
    const float* bk = (const float*)d_in[4];
    const float* Wv = (const float*)d_in[5];
    const float* bv = (const float*)d_in[6];
    const float* Wo = (const float*)d_in[7];
    const float* bo = (const float*)d_in[8];
    float* out = (float*)d_out;

    cudaFuncSetAttribute(qkv_mma, cudaFuncAttributeMaxDynamicSharedMemorySize, GSMEM);
    cudaFuncSetAttribute(out_mma, cudaFuncAttributeMaxDynamicSharedMemorySize, GSMEM);
    cudaFuncSetAttribute(attn_mma, cudaFuncAttributeMaxDynamicSharedMemorySize, ASMEM);

    __half* xh  = nullptr; cudaGetSymbolAddress((void**)&xh,  g_xh);
    __half* wvh = nullptr; cudaGetSymbolAddress((void**)&wvh, g_wvh);
    __half* wt  = nullptr; cudaGetSymbolAddress((void**)&wt,  g_wt);
    __half* woh = nullptr; cudaGetSymbolAddress((void**)&woh, g_woh);

    cvt_f32_f16<<<(M_ * D_) / 1024, 256>>>(X, xh, M_ * D_);
    cvt_f32_f16<<<(D_ * D_) / 1024, 256>>>(Wo, woh, D_ * D_);
    wtrans<<<dim3(2, 32, 48), dim3(32, 8)>>>(Wq, Wk, Wv);

    qkv_mma<<<dim3(H_ / 4, M_ / 128, 3), 256, GSMEM>>>(xh, wt, bq, bk, bv);
    attn_mma<<<dim3(S_ / 128, B_ * H_), 256, ASMEM>>>();
    out_mma<<<dim3(D_ / 256, M_ / 128), 256, GSMEM>>>(wvh, woh, bo, out);
}

// round 9
// speedup vs baseline: 1.1082x; 1.1082x over previous
#include <cuda_runtime.h>
#include <cuda_fp16.h>
#include <math.h>
#include <stdint.h>

#define B_ 4
#define S_ 2048
#define D_ 1024
#define H_ 16
#define HD_ 64
#define M_ (B_*S_)   // 8192

// fp16 scratch
__device__ __half g_qh[(size_t)B_*H_*S_*HD_];
__device__ __half g_kh[(size_t)B_*H_*S_*HD_];
__device__ __half g_vh[(size_t)B_*H_*S_*HD_];
__device__ __half g_xh[(size_t)M_*D_];
__device__ __half g_wvh[(size_t)M_*D_];
__device__ __half g_wt[(size_t)3*H_*HD_*D_];    // [z][h][n=64][k=1024]
__device__ __half g_woh[(size_t)D_*D_];         // [n][k]

// ---------------------------------------------------------------------------
__device__ __forceinline__ uint32_t smem_u32(const void* p) {
    uint32_t a;
    asm("{ .reg .u64 t; cvta.to.shared.u64 t, %1; cvt.u32.u64 %0, t; }" : "=r"(a) : "l"(p));
    return a;
}
__device__ __forceinline__ void cpa16(uint32_t dst, const void* src) {
    asm volatile("cp.async.cg.shared.global [%0], [%1], 16;" :: "r"(dst), "l"(src));
}
__device__ __forceinline__ void cpa_commit() {
    asm volatile("cp.async.commit_group;" ::: "memory");
}
__device__ __forceinline__ float ex2(float x) {
    float r; asm("ex2.approx.ftz.f32 %0, %1;" : "=f"(r) : "f"(x)); return r;
}
__device__ __forceinline__ void mma16816(float c[4], const uint32_t a[4], const uint32_t b[2]) {
    asm volatile("mma.sync.aligned.m16n8k16.row.col.f32.f16.f16.f32 "
                 "{%0,%1,%2,%3}, {%4,%5,%6,%7}, {%8,%9}, {%0,%1,%2,%3};"
                 : "+f"(c[0]), "+f"(c[1]), "+f"(c[2]), "+f"(c[3])
                 : "r"(a[0]), "r"(a[1]), "r"(a[2]), "r"(a[3]), "r"(b[0]), "r"(b[1]));
}

// =================== GEMM (exact R7 config: 423us baseline) ================
#define RS2 144
#define TILE2 (128 * RS2)          // 18432 B
#define STAGE2 (2 * TILE2)         // 36864 B (A+B)
#define GSMEM (3 * STAGE2)         // 110592 B
#define NKT2 16                    // 1024 / 64

__device__ __forceinline__ void load_stage(uint32_t sbase,
                                           const __half* __restrict__ A,
                                           const __half* __restrict__ Bg,
                                           int kt, int tid) {
    const uint32_t sA = sbase, sB = sbase + TILE2;
    #pragma unroll
    for (int i = 0; i < 4; ++i) {
        int idx = tid + i * 256;
        int row = idx >> 3, c = idx & 7;
        const size_t go = (size_t)row * D_ + kt * 64 + c * 8;
        cpa16(sA + row * RS2 + c * 16, A + go);
        cpa16(sB + row * RS2 + c * 16, Bg + go);
    }
}

__device__ __forceinline__ void load_frags(uint32_t sA, uint32_t sB, int ks,
                                           int warp_m, int warp_n, int lane,
                                           uint32_t a[4][4], uint32_t b[4][2]) {
    #pragma unroll
    for (int i = 0; i < 4; ++i) {
        int row = warp_m * 64 + i * 16 + (lane & 15);
        uint32_t addr = sA + row * RS2 + (ks * 16 + (lane >> 4) * 8) * 2;
        asm volatile("ldmatrix.sync.aligned.m8n8.x4.shared.b16 {%0,%1,%2,%3}, [%4];"
                     : "=r"(a[i][0]), "=r"(a[i][1]), "=r"(a[i][2]), "=r"(a[i][3])
                     : "r"(addr));
    }
    #pragma unroll
    for (int jj = 0; jj < 2; ++jj) {
        int g = lane >> 3, lr = lane & 7;
        int n = warp_n * 32 + jj * 16 + (g >> 1) * 8 + lr;
        uint32_t addr = sB + n * RS2 + (ks * 16 + (g & 1) * 8) * 2;
        uint32_t r0, r1, r2, r3;
        asm volatile("ldmatrix.sync.aligned.m8n8.x4.shared.b16 {%0,%1,%2,%3}, [%4];"
                     : "=r"(r0), "=r"(r1), "=r"(r2), "=r"(r3) : "r"(addr));
        b[jj * 2][0] = r0; b[jj * 2][1] = r1;
        b[jj * 2 + 1][0] = r2; b[jj * 2 + 1][1] = r3;
    }
}

__device__ __forceinline__ void do_mmas(const uint32_t a[4][4], const uint32_t b[4][2],
                                        float c[4][4][4]) {
    #pragma unroll
    for (int i = 0; i < 4; ++i)
        #pragma unroll
        for (int j = 0; j < 4; ++j)
            mma16816(c[i][j], a[i], b[j]);
}

__device__ __forceinline__ void gemm_main(uint32_t s, const __half* __restrict__ A,
                                          const __half* __restrict__ Bg,
                                          int tid, int warp_m, int warp_n, int lane,
                                          float c[4][4][4]) {
    load_stage(s + 0 * STAGE2, A, Bg, 0, tid); cpa_commit();
    load_stage(s + 1 * STAGE2, A, Bg, 1, tid); cpa_commit();

    uint32_t af[2][4][4], bf[2][4][2];

    #pragma unroll 1
    for (int kt = 0; kt < NKT2; ++kt) {
        if (kt < NKT2 - 1) asm volatile("cp.async.wait_group 1;" ::: "memory");
        else               asm volatile("cp.async.wait_group 0;" ::: "memory");
        __syncthreads();
        if (kt + 2 < NKT2) {
            load_stage(s + ((kt + 2) % 3) * STAGE2, A, Bg, kt + 2, tid);
            cpa_commit();
        }
        const uint32_t sA = s + (kt % 3) * STAGE2, sB = sA + TILE2;

        load_frags(sA, sB, 0, warp_m, warp_n, lane, af[0], bf[0]);
        #pragma unroll
        for (int ks = 0; ks < 4; ++ks) {
            if (ks < 3)
                load_frags(sA, sB, ks + 1, warp_m, warp_n, lane,
                           af[(ks + 1) & 1], bf[(ks + 1) & 1]);
            do_mmas(af[ks & 1], bf[ks & 1], c);
        }
    }
}

// ---------------------------------------------------------------------------
// QKV projection -> fp16 Q/K/V (R7 config)
// ---------------------------------------------------------------------------
__global__ __launch_bounds__(256, 2) void qkv_mma(
    const __half* __restrict__ Xh, const __half* __restrict__ Wt,
    const float* __restrict__ bq, const float* __restrict__ bk,
    const float* __restrict__ bv) {
    extern __shared__ __align__(16) char sm[];
    const uint32_t s = smem_u32(sm);
    const int tid = threadIdx.x, lane = tid & 31, wid = tid >> 5;
    const int warp_m = wid & 1, warp_n = wid >> 1;
    const int z = blockIdx.z, h0 = blockIdx.x * 2, m0 = blockIdx.y * 128;

    const __half* A  = Xh + (size_t)m0 * D_;
    const __half* Bg = Wt + ((size_t)(z * H_ + h0) * HD_) * D_;
    const float* bias = (z == 0) ? bq : (z == 1) ? bk : bv;
    __half* out       = (z == 0) ? g_qh : (z == 1) ? g_kh : g_vh;

    float c[4][4][4] = {};
    gemm_main(s, A, Bg, tid, warp_m, warp_n, lane, c);

    #pragma unroll
    for (int i = 0; i < 4; ++i) {
        #pragma unroll
        for (int j = 0; j < 4; ++j) {
            const int n = warp_n * 32 + j * 8 + (lane & 3) * 2;
            const int head = h0 + (n >> 6), e = n & 63;
            const float b0 = bias[head * HD_ + e], b1 = bias[head * HD_ + e + 1];
            #pragma unroll
            for (int half_ = 0; half_ < 2; ++half_) {
                const int m = m0 + warp_m * 64 + i * 16 + (lane >> 2) + half_ * 8;
                const int bb = m >> 11, sI = m & 2047;
                __half2 hv = __floats2half2_rn(c[i][j][half_ * 2 + 0] + b0,
                                               c[i][j][half_ * 2 + 1] + b1);
                *(__half2*)(out + (((size_t)(bb * H_ + head) * S_ + sI) * HD_ + e)) = hv;
            }
        }
    }
}

// ---------------------------------------------------------------------------
// Output projection: C = WVh * Woh^T + bo (R7 config)
// ---------------------------------------------------------------------------
__global__ __launch_bounds__(256, 2) void out_mma(
    const __half* __restrict__ WVh, const __half* __restrict__ Woh,
    const float* __restrict__ bo, float* __restrict__ outp) {
    extern __shared__ __align__(16) char sm[];
    const uint32_t s = smem_u32(sm);
    const int tid = threadIdx.x, lane = tid & 31, wid = tid >> 5;
    const int warp_m = wid & 1, warp_n = wid >> 1;
    const int n0 = blockIdx.x * 128, m0 = blockIdx.y * 128;

    const __half* A  = WVh + (size_t)m0 * D_;
    const __half* Bg = Woh + (size_t)n0 * D_;

    float c[4][4][4] = {};
    gemm_main(s, A, Bg, tid, warp_m, warp_n, lane, c);

    #pragma unroll
    for (int i = 0; i < 4; ++i) {
        #pragma unroll
        for (int j = 0; j < 4; ++j) {
            const int n = n0 + warp_n * 32 + j * 8 + (lane & 3) * 2;
            const float b0 = bo[n], b1 = bo[n + 1];
            #pragma unroll
            for (int half_ = 0; half_ < 2; ++half_) {
                const int m = m0 + warp_m * 64 + i * 16 + (lane >> 2) + half_ * 8;
                float2 v;
                v.x = c[i][j][half_ * 2 + 0] + b0;
                v.y = c[i][j][half_ * 2 + 1] + b1;
                *(float2*)(outp + (size_t)m * D_ + n) = v;
            }
        }
    }
}

// ============ attention: heavy-first order + x4 fragment loads ==============
#define ARS 144
#define ATILE (64 * ARS)
#define ASTG (2 * ATILE)
#define ASMEM (3 * ASTG)           // 55296 B

__global__ __launch_bounds__(256) void attn_mma() {
    extern __shared__ __align__(16) char sm[];
    const uint32_t s = smem_u32(sm);
    const int tid = threadIdx.x, lane = tid & 31, w = tid >> 5;
    const int bh = blockIdx.y;
    const int q0 = (gridDim.x - 1 - blockIdx.x) * 128;   // heavy tiles first

    const __half* __restrict__ Qb = g_qh + (size_t)bh * S_ * HD_;
    const __half* __restrict__ Kb = g_kh + (size_t)bh * S_ * HD_;
    const __half* __restrict__ Vb = g_vh + (size_t)bh * S_ * HD_;

    const int r0 = q0 + w * 16 + (lane >> 2);
    const int cq = lane & 3;
    uint32_t qf[4][4];
    {
        const __half2* Qr0 = (const __half2*)(Qb + (size_t)r0 * HD_);
        const __half2* Qr1 = (const __half2*)(Qb + (size_t)(r0 + 8) * HD_);
        #pragma unroll
        for (int t = 0; t < 4; ++t) {
            qf[t][0] = *(const uint32_t*)&Qr0[t * 8 + cq];
            qf[t][1] = *(const uint32_t*)&Qr1[t * 8 + cq];
            qf[t][2] = *(const uint32_t*)&Qr0[t * 8 + 4 + cq];
            qf[t][3] = *(const uint32_t*)&Qr1[t * 8 + 4 + cq];
        }
    }

    float o[8][4];
    #pragma unroll
    for (int j = 0; j < 8; ++j)
        #pragma unroll
        for (int x = 0; x < 4; ++x) o[j][x] = 0.f;
    float m0 = -INFINITY, m1 = -INFINITY, l0 = 0.f, l1 = 0.f;

    const int NT = (q0 + 128) / 64;
    const float SC = 0.18033688f;

    auto load_tile = [&](int kt, int stg) {
        const uint32_t base = s + stg * ASTG;
        #pragma unroll
        for (int i = 0; i < 2; ++i) {
            int idx = tid + i * 256;
            int row = idx >> 3, c = idx & 7;
            const size_t go = (size_t)(kt * 64 + row) * HD_ + c * 8;
            cpa16(base + row * ARS + c * 16, Kb + go);
            cpa16(base + ATILE + row * ARS + c * 16, Vb + go);
        }
    };

    load_tile(0, 0); cpa_commit();
    if (NT > 1) { load_tile(1, 1); cpa_commit(); }

    const int g = lane >> 3, lr = lane & 7;

    #pragma unroll 1
    for (int kt = 0; kt < NT; ++kt) {
        const int k0 = kt * 64;
        if (kt < NT - 1) asm volatile("cp.async.wait_group 1;" ::: "memory");
        else             asm volatile("cp.async.wait_group 0;" ::: "memory");
        __syncthreads();
        if (kt + 2 < NT) { load_tile(kt + 2, (kt + 2) % 3); cpa_commit(); }

        const uint32_t sK = s + (kt % 3) * ASTG, sV = sK + ATILE;

        // ---- S = Q K^T : x4 K loads (2 n-blocks per ldmatrix) ----
        float sa[8][4];
        #pragma unroll
        for (int j = 0; j < 8; ++j)
            #pragma unroll
            for (int x = 0; x < 4; ++x) sa[j][x] = 0.f;
        #pragma unroll
        for (int t = 0; t < 4; ++t) {
            uint32_t kb[8][2];
            #pragma unroll
            for (int jp = 0; jp < 4; ++jp) {
                const int n = jp * 16 + (g >> 1) * 8 + lr;
                uint32_t addr = sK + n * ARS + t * 32 + (g & 1) * 16;
                uint32_t r0_, r1_, r2_, r3_;
                asm volatile("ldmatrix.sync.aligned.m8n8.x4.shared.b16 {%0,%1,%2,%3}, [%4];"
                             : "=r"(r0_), "=r"(r1_), "=r"(r2_), "=r"(r3_) : "r"(addr));
                kb[jp * 2][0] = r0_; kb[jp * 2][1] = r1_;
                kb[jp * 2 + 1][0] = r2_; kb[jp * 2 + 1][1] = r3_;
            }
            #pragma unroll
            for (int j = 0; j < 8; ++j)
                mma16816(sa[j], qf[t], kb[j]);
        }

        // ---- mask + online softmax ----
        const bool needmask = (k0 + 63 > r0);
        float tm0 = -INFINITY, tm1 = -INFINITY;
        #pragma unroll
        for (int j = 0; j < 8; ++j) {
            float v0 = sa[j][0] * SC, v1 = sa[j][1] * SC;
            float v2 = sa[j][2] * SC, v3 = sa[j][3] * SC;
            if (needmask) {
                const int col = k0 + j * 8 + (lane & 3) * 2;
                if (col > r0)         v0 = -INFINITY;
                if (col + 1 > r0)     v1 = -INFINITY;
                if (col > r0 + 8)     v2 = -INFINITY;
                if (col + 1 > r0 + 8) v3 = -INFINITY;
            }
            sa[j][0] = v0; sa[j][1] = v1; sa[j][2] = v2; sa[j][3] = v3;
            tm0 = fmaxf(tm0, fmaxf(v0, v1));
            tm1 = fmaxf(tm1, fmaxf(v2, v3));
        }
        tm0 = fmaxf(tm0, __shfl_xor_sync(0xffffffffu, tm0, 1));
        tm0 = fmaxf(tm0, __shfl_xor_sync(0xffffffffu, tm0, 2));
        tm1 = fmaxf(tm1, __shfl_xor_sync(0xffffffffu, tm1, 1));
        tm1 = fmaxf(tm1, __shfl_xor_sync(0xffffffffu, tm1, 2));

        const float mn0 = fmaxf(m0, tm0), mn1 = fmaxf(m1, tm1);
        const float c0 = ex2(m0 - mn0), c1 = ex2(m1 - mn1);
        m0 = mn0; m1 = mn1;

        float ts0 = 0.f, ts1 = 0.f;
        uint32_t pa[4][4];
        #pragma unroll
        for (int j = 0; j < 8; ++j) {
            const float p0 = ex2(sa[j][0] - mn0), p1 = ex2(sa[j][1] - mn0);
            const float p2 = ex2(sa[j][2] - mn1), p3 = ex2(sa[j][3] - mn1);
            ts0 += p0 + p1; ts1 += p2 + p3;
            const __half2 h01 = __floats2half2_rn(p0, p1);
            const __half2 h23 = __floats2half2_rn(p2, p3);
            const int t = j >> 1;
            if ((j & 1) == 0) {
                pa[t][0] = *(const uint32_t*)&h01;
                pa[t][1] = *(const uint32_t*)&h23;
            } else {
                pa[t][2] = *(const uint32_t*)&h01;
                pa[t][3] = *(const uint32_t*)&h23;
            }
        }
        ts0 += __shfl_xor_sync(0xffffffffu, ts0, 1);
        ts0 += __shfl_xor_sync(0xffffffffu, ts0, 2);
        ts1 += __shfl_xor_sync(0xffffffffu, ts1, 1);
        ts1 += __shfl_xor_sync(0xffffffffu, ts1, 2);
        l0 = l0 * c0 + ts0;
        l1 = l1 * c1 + ts1;

        #pragma unroll
        for (int j = 0; j < 8; ++j) {
            o[j][0] *= c0; o[j][1] *= c0;
            o[j][2] *= c1; o[j][3] *= c1;
        }

        // ---- O += P V : x4.trans V loads (2 n-blocks per ldmatrix) ----
        #pragma unroll
        for (int t = 0; t < 4; ++t) {
            uint32_t vb[8][2];
            #pragma unroll
            for (int jp = 0; jp < 4; ++jp) {
                const int row = t * 16 + (g & 1) * 8 + lr;
                uint32_t addr = sV + row * ARS + jp * 32 + (g >> 1) * 16;
                uint32_t r0_, r1_, r2_, r3_;
                asm volatile("ldmatrix.sync.aligned.m8n8.x4.trans.shared.b16 {%0,%1,%2,%3}, [%4];"
                             : "=r"(r0_), "=r"(r1_), "=r"(r2_), "=r"(r3_) : "r"(addr));
                vb[jp * 2][0] = r0_; vb[jp * 2][1] = r1_;
                vb[jp * 2 + 1][0] = r2_; vb[jp * 2 + 1][1] = r3_;
            }
            #pragma unroll
            for (int j = 0; j < 8; ++j)
                mma16816(o[j], pa[t], vb[j]);
        }
    }

    // ---- epilogue ----
    const float i0 = 1.f / l0, i1 = 1.f / l1;
    const int b = bh >> 4, h = bh & 15;
    __half* out0 = g_wvh + ((size_t)(b * S_) + r0) * D_ + h * HD_ + (lane & 3) * 2;
    __half* out1 = g_wvh + ((size_t)(b * S_) + r0 + 8) * D_ + h * HD_ + (lane & 3) * 2;
    #pragma unroll
    for (int j = 0; j < 8; ++j) {
        *(__half2*)(out0 + j * 8) = __floats2half2_rn(o[j][0] * i0, o[j][1] * i0);
        *(__half2*)(out1 + j * 8) = __floats2half2_rn(o[j][2] * i1, o[j][3] * i1);
    }
}

// ---------------------------------------------------------------------------
// converts + weight transpose
// ---------------------------------------------------------------------------
__global__ void cvt_f32_f16(const float* __restrict__ in, __half* __restrict__ out, int n) {
    int i = (blockIdx.x * blockDim.x + threadIdx.x) * 4;
    if (i < n) {
        float4 v = *(const float4*)(in + i);
        __half2* o = (__half2*)(out + i);
        o[0] = __floats2half2_rn(v.x, v.y);
        o[1] = __floats2half2_rn(v.z, v.w);
    }
}

__global__ void wtrans(const float* __restrict__ Wq, const float* __restrict__ Wk,
                       const float* __restrict__ Wv) {
    __shared__ float t[32][33];
    const int zh = blockIdx.z, z = zh >> 4, h = zh & 15;
    const float* W = ((z == 0) ? Wq : (z == 1) ? Wk : Wv) + (size_t)h * D_ * HD_;
    __half* out = g_wt + (size_t)zh * HD_ * D_;
    const int n0 = blockIdx.x * 32, k0 = blockIdx.y * 32;
    const int tx = threadIdx.x, ty = threadIdx.y;
    #pragma unroll
    for (int i = 0; i < 32; i += 8)
        t[ty + i][tx] = W[(size_t)(k0 + ty + i) * HD_ + n0 + tx];
    __syncthreads();
    #pragma unroll
    for (int i = 0; i < 32; i += 8)
        out[(size_t)(n0 + ty + i) * D_ + k0 + tx] = __float2half_rn(t[tx][ty + i]);
}

// ---------------------------------------------------------------------------
extern "C" void kernel_launch(void* const* d_in, const int* in_sizes, int n_in,
                              void* d_out, int out_size) {
    const float* X  = (const float*)d_in[0];
    const float* Wq = (const float*)d_in[1];
    const float* bq = (const float*)d_in[2];
    const float* Wk = (const float*)d_in[3];
    const float* bk = (const float*)d_in[4];
    const float* Wv = (const float*)d_in[5];
    const float* bv = (const float*)d_in[6];
    const float* Wo = (const float*)d_in[7];
    const float* bo = (const float*)d_in[8];
    float* out = (float*)d_out;

    cudaFuncSetAttribute(qkv_mma, cudaFuncAttributeMaxDynamicSharedMemorySize, GSMEM);
    cudaFuncSetAttribute(out_mma, cudaFuncAttributeMaxDynamicSharedMemorySize, GSMEM);
    cudaFuncSetAttribute(attn_mma, cudaFuncAttributeMaxDynamicSharedMemorySize, ASMEM);

    __half* xh  = nullptr; cudaGetSymbolAddress((void**)&xh,  g_xh);
    __half* wvh = nullptr; cudaGetSymbolAddress((void**)&wvh, g_wvh);
    __half* wt  = nullptr; cudaGetSymbolAddress((void**)&wt,  g_wt);
    __half* woh = nullptr; cudaGetSymbolAddress((void**)&woh, g_woh);

    cvt_f32_f16<<<(M_ * D_) / 1024, 256>>>(X, xh, M_ * D_);
    cvt_f32_f16<<<(D_ * D_) / 1024, 256>>>(Wo, woh, D_ * D_);
    wtrans<<<dim3(2, 32, 48), dim3(32, 8)>>>(Wq, Wk, Wv);

    qkv_mma<<<dim3(H_ / 2, M_ / 128, 3), 256, GSMEM>>>(xh, wt, bq, bk, bv);
    attn_mma<<<dim3(S_ / 128, B_ * H_), 256, ASMEM>>>();
    out_mma<<<dim3(D_ / 128, M_ / 128), 256, GSMEM>>>(wvh, woh, bo, out);
}

// round 10
// speedup vs baseline: 1.1117x; 1.0032x over previous
#include <cuda_runtime.h>
#include <cuda_fp16.h>
#include <math.h>
#include <stdint.h>

#define B_ 4
#define S_ 2048
#define D_ 1024
#define H_ 16
#define HD_ 64
#define M_ (B_*S_)   // 8192

// fp16 scratch
__device__ __half g_qh[(size_t)B_*H_*S_*HD_];
__device__ __half g_kh[(size_t)B_*H_*S_*HD_];
__device__ __half g_vh[(size_t)B_*H_*S_*HD_];
__device__ __half g_xh[(size_t)M_*D_];
__device__ __half g_wvh[(size_t)M_*D_];
__device__ __half g_wt[(size_t)3*H_*HD_*D_];    // [z][h][n=64][k=1024]
__device__ __half g_woh[(size_t)D_*D_];         // [n][k]

// ---------------------------------------------------------------------------
__device__ __forceinline__ uint32_t smem_u32(const void* p) {
    uint32_t a;
    asm("{ .reg .u64 t; cvta.to.shared.u64 t, %1; cvt.u32.u64 %0, t; }" : "=r"(a) : "l"(p));
    return a;
}
__device__ __forceinline__ void cpa16(uint32_t dst, const void* src) {
    asm volatile("cp.async.cg.shared.global [%0], [%1], 16;" :: "r"(dst), "l"(src));
}
__device__ __forceinline__ void cpa_commit() {
    asm volatile("cp.async.commit_group;" ::: "memory");
}
__device__ __forceinline__ float ex2(float x) {
    float r; asm("ex2.approx.ftz.f32 %0, %1;" : "=f"(r) : "f"(x)); return r;
}
__device__ __forceinline__ void mma16816(float c[4], const uint32_t a[4], const uint32_t b[2]) {
    asm volatile("mma.sync.aligned.m16n8k16.row.col.f32.f16.f16.f32 "
                 "{%0,%1,%2,%3}, {%4,%5,%6,%7}, {%8,%9}, {%0,%1,%2,%3};"
                 : "+f"(c[0]), "+f"(c[1]), "+f"(c[2]), "+f"(c[3])
                 : "r"(a[0]), "r"(a[1]), "r"(a[2]), "r"(a[3]), "r"(b[0]), "r"(b[1]));
}

// =================== GEMM (exact R7/R9 config) =============================
#define RS2 144
#define TILE2 (128 * RS2)          // 18432 B
#define STAGE2 (2 * TILE2)         // 36864 B (A+B)
#define GSMEM (3 * STAGE2)         // 110592 B
#define NKT2 16                    // 1024 / 64

__device__ __forceinline__ void load_stage(uint32_t sbase,
                                           const __half* __restrict__ A,
                                           const __half* __restrict__ Bg,
                                           int kt, int tid) {
    const uint32_t sA = sbase, sB = sbase + TILE2;
    #pragma unroll
    for (int i = 0; i < 4; ++i) {
        int idx = tid + i * 256;
        int row = idx >> 3, c = idx & 7;
        const size_t go = (size_t)row * D_ + kt * 64 + c * 8;
        cpa16(sA + row * RS2 + c * 16, A + go);
        cpa16(sB + row * RS2 + c * 16, Bg + go);
    }
}

__device__ __forceinline__ void load_frags(uint32_t sA, uint32_t sB, int ks,
                                           int warp_m, int warp_n, int lane,
                                           uint32_t a[4][4], uint32_t b[4][2]) {
    #pragma unroll
    for (int i = 0; i < 4; ++i) {
        int row = warp_m * 64 + i * 16 + (lane & 15);
        uint32_t addr = sA + row * RS2 + (ks * 16 + (lane >> 4) * 8) * 2;
        asm volatile("ldmatrix.sync.aligned.m8n8.x4.shared.b16 {%0,%1,%2,%3}, [%4];"
                     : "=r"(a[i][0]), "=r"(a[i][1]), "=r"(a[i][2]), "=r"(a[i][3])
                     : "r"(addr));
    }
    #pragma unroll
    for (int jj = 0; jj < 2; ++jj) {
        int g = lane >> 3, lr = lane & 7;
        int n = warp_n * 32 + jj * 16 + (g >> 1) * 8 + lr;
        uint32_t addr = sB + n * RS2 + (ks * 16 + (g & 1) * 8) * 2;
        uint32_t r0, r1, r2, r3;
        asm volatile("ldmatrix.sync.aligned.m8n8.x4.shared.b16 {%0,%1,%2,%3}, [%4];"
                     : "=r"(r0), "=r"(r1), "=r"(r2), "=r"(r3) : "r"(addr));
        b[jj * 2][0] = r0; b[jj * 2][1] = r1;
        b[jj * 2 + 1][0] = r2; b[jj * 2 + 1][1] = r3;
    }
}

__device__ __forceinline__ void do_mmas(const uint32_t a[4][4], const uint32_t b[4][2],
                                        float c[4][4][4]) {
    #pragma unroll
    for (int i = 0; i < 4; ++i)
        #pragma unroll
        for (int j = 0; j < 4; ++j)
            mma16816(c[i][j], a[i], b[j]);
}

__device__ __forceinline__ void gemm_main(uint32_t s, const __half* __restrict__ A,
                                          const __half* __restrict__ Bg,
                                          int tid, int warp_m, int warp_n, int lane,
                                          float c[4][4][4]) {
    load_stage(s + 0 * STAGE2, A, Bg, 0, tid); cpa_commit();
    load_stage(s + 1 * STAGE2, A, Bg, 1, tid); cpa_commit();

    uint32_t af[2][4][4], bf[2][4][2];

    #pragma unroll 1
    for (int kt = 0; kt < NKT2; ++kt) {
        if (kt < NKT2 - 1) asm volatile("cp.async.wait_group 1;" ::: "memory");
        else               asm volatile("cp.async.wait_group 0;" ::: "memory");
        __syncthreads();
        if (kt + 2 < NKT2) {
            load_stage(s + ((kt + 2) % 3) * STAGE2, A, Bg, kt + 2, tid);
            cpa_commit();
        }
        const uint32_t sA = s + (kt % 3) * STAGE2, sB = sA + TILE2;

        load_frags(sA, sB, 0, warp_m, warp_n, lane, af[0], bf[0]);
        #pragma unroll
        for (int ks = 0; ks < 4; ++ks) {
            if (ks < 3)
                load_frags(sA, sB, ks + 1, warp_m, warp_n, lane,
                           af[(ks + 1) & 1], bf[(ks + 1) & 1]);
            do_mmas(af[ks & 1], bf[ks & 1], c);
        }
    }
}

// ---------------------------------------------------------------------------
// QKV projection -> fp16 Q/K/V
// ---------------------------------------------------------------------------
__global__ __launch_bounds__(256, 2) void qkv_mma(
    const __half* __restrict__ Xh, const __half* __restrict__ Wt,
    const float* __restrict__ bq, const float* __restrict__ bk,
    const float* __restrict__ bv) {
    extern __shared__ __align__(16) char sm[];
    const uint32_t s = smem_u32(sm);
    const int tid = threadIdx.x, lane = tid & 31, wid = tid >> 5;
    const int warp_m = wid & 1, warp_n = wid >> 1;
    const int z = blockIdx.z, h0 = blockIdx.x * 2, m0 = blockIdx.y * 128;

    const __half* A  = Xh + (size_t)m0 * D_;
    const __half* Bg = Wt + ((size_t)(z * H_ + h0) * HD_) * D_;
    const float* bias = (z == 0) ? bq : (z == 1) ? bk : bv;
    __half* out       = (z == 0) ? g_qh : (z == 1) ? g_kh : g_vh;

    float c[4][4][4] = {};
    gemm_main(s, A, Bg, tid, warp_m, warp_n, lane, c);

    #pragma unroll
    for (int i = 0; i < 4; ++i) {
        #pragma unroll
        for (int j = 0; j < 4; ++j) {
            const int n = warp_n * 32 + j * 8 + (lane & 3) * 2;
            const int head = h0 + (n >> 6), e = n & 63;
            const float b0 = bias[head * HD_ + e], b1 = bias[head * HD_ + e + 1];
            #pragma unroll
            for (int half_ = 0; half_ < 2; ++half_) {
                const int m = m0 + warp_m * 64 + i * 16 + (lane >> 2) + half_ * 8;
                const int bb = m >> 11, sI = m & 2047;
                __half2 hv = __floats2half2_rn(c[i][j][half_ * 2 + 0] + b0,
                                               c[i][j][half_ * 2 + 1] + b1);
                *(__half2*)(out + (((size_t)(bb * H_ + head) * S_ + sI) * HD_ + e)) = hv;
            }
        }
    }
}

// ---------------------------------------------------------------------------
// Output projection: C = WVh * Woh^T + bo
// ---------------------------------------------------------------------------
__global__ __launch_bounds__(256, 2) void out_mma(
    const __half* __restrict__ WVh, const __half* __restrict__ Woh,
    const float* __restrict__ bo, float* __restrict__ outp) {
    extern __shared__ __align__(16) char sm[];
    const uint32_t s = smem_u32(sm);
    const int tid = threadIdx.x, lane = tid & 31, wid = tid >> 5;
    const int warp_m = wid & 1, warp_n = wid >> 1;
    const int n0 = blockIdx.x * 128, m0 = blockIdx.y * 128;

    const __half* A  = WVh + (size_t)m0 * D_;
    const __half* Bg = Woh + (size_t)n0 * D_;

    float c[4][4][4] = {};
    gemm_main(s, A, Bg, tid, warp_m, warp_n, lane, c);

    #pragma unroll
    for (int i = 0; i < 4; ++i) {
        #pragma unroll
        for (int j = 0; j < 4; ++j) {
            const int n = n0 + warp_n * 32 + j * 8 + (lane & 3) * 2;
            const float b0 = bo[n], b1 = bo[n + 1];
            #pragma unroll
            for (int half_ = 0; half_ < 2; ++half_) {
                const int m = m0 + warp_m * 64 + i * 16 + (lane >> 2) + half_ * 8;
                float2 v;
                v.x = c[i][j][half_ * 2 + 0] + b0;
                v.y = c[i][j][half_ * 2 + 1] + b1;
                *(float2*)(outp + (size_t)m * D_ + n) = v;
            }
        }
    }
}

// ============ attention (R9 + Q pre-scale in fp16) ==========================
#define ARS 144
#define ATILE (64 * ARS)
#define ASTG (2 * ATILE)
#define ASMEM (3 * ASTG)           // 55296 B

__global__ __launch_bounds__(256) void attn_mma() {
    extern __shared__ __align__(16) char sm[];
    const uint32_t s = smem_u32(sm);
    const int tid = threadIdx.x, lane = tid & 31, w = tid >> 5;
    const int bh = blockIdx.y;
    const int q0 = (gridDim.x - 1 - blockIdx.x) * 128;   // heavy tiles first

    const __half* __restrict__ Qb = g_qh + (size_t)bh * S_ * HD_;
    const __half* __restrict__ Kb = g_kh + (size_t)bh * S_ * HD_;
    const __half* __restrict__ Vb = g_vh + (size_t)bh * S_ * HD_;

    const int r0 = q0 + w * 16 + (lane >> 2);
    const int cq = lane & 3;
    const float SC = 0.18033688f;                 // 0.125 * log2(e)
    uint32_t qf[4][4];
    {
        const __half2 sc2 = __floats2half2_rn(SC, SC);
        const __half2* Qr0 = (const __half2*)(Qb + (size_t)r0 * HD_);
        const __half2* Qr1 = (const __half2*)(Qb + (size_t)(r0 + 8) * HD_);
        #pragma unroll
        for (int t = 0; t < 4; ++t) {
            __half2 v0 = __hmul2(Qr0[t * 8 + cq], sc2);
            __half2 v1 = __hmul2(Qr1[t * 8 + cq], sc2);
            __half2 v2 = __hmul2(Qr0[t * 8 + 4 + cq], sc2);
            __half2 v3 = __hmul2(Qr1[t * 8 + 4 + cq], sc2);
            qf[t][0] = *(const uint32_t*)&v0;
            qf[t][1] = *(const uint32_t*)&v1;
            qf[t][2] = *(const uint32_t*)&v2;
            qf[t][3] = *(const uint32_t*)&v3;
        }
    }

    float o[8][4];
    #pragma unroll
    for (int j = 0; j < 8; ++j)
        #pragma unroll
        for (int x = 0; x < 4; ++x) o[j][x] = 0.f;
    float m0 = -INFINITY, m1 = -INFINITY, l0 = 0.f, l1 = 0.f;

    const int NT = (q0 + 128) / 64;

    auto load_tile = [&](int kt, int stg) {
        const uint32_t base = s + stg * ASTG;
        #pragma unroll
        for (int i = 0; i < 2; ++i) {
            int idx = tid + i * 256;
            int row = idx >> 3, c = idx & 7;
            const size_t go = (size_t)(kt * 64 + row) * HD_ + c * 8;
            cpa16(base + row * ARS + c * 16, Kb + go);
            cpa16(base + ATILE + row * ARS + c * 16, Vb + go);
        }
    };

    load_tile(0, 0); cpa_commit();
    if (NT > 1) { load_tile(1, 1); cpa_commit(); }

    const int g = lane >> 3, lr = lane & 7;

    #pragma unroll 1
    for (int kt = 0; kt < NT; ++kt) {
        const int k0 = kt * 64;
        if (kt < NT - 1) asm volatile("cp.async.wait_group 1;" ::: "memory");
        else             asm volatile("cp.async.wait_group 0;" ::: "memory");
        __syncthreads();
        if (kt + 2 < NT) { load_tile(kt + 2, (kt + 2) % 3); cpa_commit(); }

        const uint32_t sK = s + (kt % 3) * ASTG, sV = sK + ATILE;

        // ---- S = (Q*sc) K^T ----
        float sa[8][4];
        #pragma unroll
        for (int j = 0; j < 8; ++j)
            #pragma unroll
            for (int x = 0; x < 4; ++x) sa[j][x] = 0.f;
        #pragma unroll
        for (int t = 0; t < 4; ++t) {
            uint32_t kb[8][2];
            #pragma unroll
            for (int jp = 0; jp < 4; ++jp) {
                const int n = jp * 16 + (g >> 1) * 8 + lr;
                uint32_t addr = sK + n * ARS + t * 32 + (g & 1) * 16;
                uint32_t r0_, r1_, r2_, r3_;
                asm volatile("ldmatrix.sync.aligned.m8n8.x4.shared.b16 {%0,%1,%2,%3}, [%4];"
                             : "=r"(r0_), "=r"(r1_), "=r"(r2_), "=r"(r3_) : "r"(addr));
                kb[jp * 2][0] = r0_; kb[jp * 2][1] = r1_;
                kb[jp * 2 + 1][0] = r2_; kb[jp * 2 + 1][1] = r3_;
            }
            #pragma unroll
            for (int j = 0; j < 8; ++j)
                mma16816(sa[j], qf[t], kb[j]);
        }

        // ---- mask + online softmax (scores already scaled) ----
        const bool needmask = (k0 + 63 > r0);
        float tm0 = -INFINITY, tm1 = -INFINITY;
        #pragma unroll
        for (int j = 0; j < 8; ++j) {
            if (needmask) {
                const int col = k0 + j * 8 + (lane & 3) * 2;
                if (col > r0)         sa[j][0] = -INFINITY;
                if (col + 1 > r0)     sa[j][1] = -INFINITY;
                if (col > r0 + 8)     sa[j][2] = -INFINITY;
                if (col + 1 > r0 + 8) sa[j][3] = -INFINITY;
            }
            tm0 = fmaxf(tm0, fmaxf(sa[j][0], sa[j][1]));
            tm1 = fmaxf(tm1, fmaxf(sa[j][2], sa[j][3]));
        }
        tm0 = fmaxf(tm0, __shfl_xor_sync(0xffffffffu, tm0, 1));
        tm0 = fmaxf(tm0, __shfl_xor_sync(0xffffffffu, tm0, 2));
        tm1 = fmaxf(tm1, __shfl_xor_sync(0xffffffffu, tm1, 1));
        tm1 = fmaxf(tm1, __shfl_xor_sync(0xffffffffu, tm1, 2));

        const float mn0 = fmaxf(m0, tm0), mn1 = fmaxf(m1, tm1);
        const float c0 = ex2(m0 - mn0), c1 = ex2(m1 - mn1);
        m0 = mn0; m1 = mn1;

        float ts0 = 0.f, ts1 = 0.f;
        uint32_t pa[4][4];
        #pragma unroll
        for (int j = 0; j < 8; ++j) {
            const float p0 = ex2(sa[j][0] - mn0), p1 = ex2(sa[j][1] - mn0);
            const float p2 = ex2(sa[j][2] - mn1), p3 = ex2(sa[j][3] - mn1);
            ts0 += p0 + p1; ts1 += p2 + p3;
            const __half2 h01 = __floats2half2_rn(p0, p1);
            const __half2 h23 = __floats2half2_rn(p2, p3);
            const int t = j >> 1;
            if ((j & 1) == 0) {
                pa[t][0] = *(const uint32_t*)&h01;
                pa[t][1] = *(const uint32_t*)&h23;
            } else {
                pa[t][2] = *(const uint32_t*)&h01;
                pa[t][3] = *(const uint32_t*)&h23;
            }
        }
        ts0 += __shfl_xor_sync(0xffffffffu, ts0, 1);
        ts0 += __shfl_xor_sync(0xffffffffu, ts0, 2);
        ts1 += __shfl_xor_sync(0xffffffffu, ts1, 1);
        ts1 += __shfl_xor_sync(0xffffffffu, ts1, 2);
        l0 = l0 * c0 + ts0;
        l1 = l1 * c1 + ts1;

        #pragma unroll
        for (int j = 0; j < 8; ++j) {
            o[j][0] *= c0; o[j][1] *= c0;
            o[j][2] *= c1; o[j][3] *= c1;
        }

        // ---- O += P V ----
        #pragma unroll
        for (int t = 0; t < 4; ++t) {
            uint32_t vb[8][2];
            #pragma unroll
            for (int jp = 0; jp < 4; ++jp) {
                const int row = t * 16 + (g & 1) * 8 + lr;
                uint32_t addr = sV + row * ARS + jp * 32 + (g >> 1) * 16;
                uint32_t r0_, r1_, r2_, r3_;
                asm volatile("ldmatrix.sync.aligned.m8n8.x4.trans.shared.b16 {%0,%1,%2,%3}, [%4];"
                             : "=r"(r0_), "=r"(r1_), "=r"(r2_), "=r"(r3_) : "r"(addr));
                vb[jp * 2][0] = r0_; vb[jp * 2][1] = r1_;
                vb[jp * 2 + 1][0] = r2_; vb[jp * 2 + 1][1] = r3_;
            }
            #pragma unroll
            for (int j = 0; j < 8; ++j)
                mma16816(o[j], pa[t], vb[j]);
        }
    }

    // ---- epilogue ----
    const float i0 = 1.f / l0, i1 = 1.f / l1;
    const int b = bh >> 4, h = bh & 15;
    __half* out0 = g_wvh + ((size_t)(b * S_) + r0) * D_ + h * HD_ + (lane & 3) * 2;
    __half* out1 = g_wvh + ((size_t)(b * S_) + r0 + 8) * D_ + h * HD_ + (lane & 3) * 2;
    #pragma unroll
    for (int j = 0; j < 8; ++j) {
        *(__half2*)(out0 + j * 8) = __floats2half2_rn(o[j][0] * i0, o[j][1] * i0);
        *(__half2*)(out1 + j * 8) = __floats2half2_rn(o[j][2] * i1, o[j][3] * i1);
    }
}

// ---------------------------------------------------------------------------
// fused prep: cvt X (blocks 0..8191), cvt Wo (8192..9215), wtrans (9216..12287)
// ---------------------------------------------------------------------------
#define NB_X  8192
#define NB_WO 1024
#define NB_WT 3072

__global__ __launch_bounds__(256) void prep(
    const float* __restrict__ X,  const float* __restrict__ Wo,
    const float* __restrict__ Wq, const float* __restrict__ Wk,
    const float* __restrict__ Wv) {
    __shared__ float t[32][33];
    const int b = blockIdx.x, tid = threadIdx.x;

    if (b < NB_X) {                       // X fp32 -> fp16 (8M elts, 4/thread)
        const int i = (b * 256 + tid) * 4;
        float4 v = *(const float4*)(X + i);
        __half2* o = (__half2*)(g_xh + i);
        o[0] = __floats2half2_rn(v.x, v.y);
        o[1] = __floats2half2_rn(v.z, v.w);
    } else if (b < NB_X + NB_WO) {        // Wo fp32 -> fp16 (1M elts)
        const int i = ((b - NB_X) * 256 + tid) * 4;
        float4 v = *(const float4*)(Wo + i);
        __half2* o = (__half2*)(g_woh + i);
        o[0] = __floats2half2_rn(v.x, v.y);
        o[1] = __floats2half2_rn(v.z, v.w);
    } else {                              // wtrans: W[h][k][n=64] -> g_wt[zh][n][k]
        const int id = b - NB_X - NB_WO;  // 0..3071  (bx=2, by=32, bz=48)
        const int bx = id & 1, by = (id >> 1) & 31, bz = id >> 6;
        const int z = bz >> 4, h = bz & 15;
        const float* W = ((z == 0) ? Wq : (z == 1) ? Wk : Wv) + (size_t)h * D_ * HD_;
        __half* out = g_wt + (size_t)bz * HD_ * D_;
        const int n0 = bx * 32, k0 = by * 32;
        const int tx = tid & 31, ty = tid >> 5;   // 32 x 8
        #pragma unroll
        for (int i = 0; i < 32; i += 8)
            t[ty + i][tx] = W[(size_t)(k0 + ty + i) * HD_ + n0 + tx];
        __syncthreads();
        #pragma unroll
        for (int i = 0; i < 32; i += 8)
            out[(size_t)(n0 + ty + i) * D_ + k0 + tx] = __float2half_rn(t[tx][ty + i]);
    }
}

// ---------------------------------------------------------------------------
extern "C" void kernel_launch(void* const* d_in, const int* in_sizes, int n_in,
                              void* d_out, int out_size) {
    const float* X  = (const float*)d_in[0];
    const float* Wq = (const float*)d_in[1];
    const float* bq = (const float*)d_in[2];
    const float* Wk = (const float*)d_in[3];
    const float* bk = (const float*)d_in[4];
    const float* Wv = (const float*)d_in[5];
    const float* bv = (const float*)d_in[6];
    const float* Wo = (const float*)d_in[7];
    const float* bo = (const float*)d_in[8];
    float* out = (float*)d_out;

    cudaFuncSetAttribute(qkv_mma, cudaFuncAttributeMaxDynamicSharedMemorySize, GSMEM);
    cudaFuncSetAttribute(out_mma, cudaFuncAttributeMaxDynamicSharedMemorySize, GSMEM);
    cudaFuncSetAttribute(attn_mma, cudaFuncAttributeMaxDynamicSharedMemorySize, ASMEM);

    __half* xh  = nullptr; cudaGetSymbolAddress((void**)&xh,  g_xh);
    __half* wvh = nullptr; cudaGetSymbolAddress((void**)&wvh, g_wvh);
    __half* wt  = nullptr; cudaGetSymbolAddress((void**)&wt,  g_wt);
    __half* woh = nullptr; cudaGetSymbolAddress((void**)&woh, g_woh);

    prep<<<NB_X + NB_WO + NB_WT, 256>>>(X, Wo, Wq, Wk, Wv);
    qkv_mma<<<dim3(H_ / 2, M_ / 128, 3), 256, GSMEM>>>(xh, wt, bq, bk, bv);
    attn_mma<<<dim3(S_ / 128, B_ * H_), 256, ASMEM>>>();
    out_mma<<<dim3(D_ / 128, M_ / 128), 256, GSMEM>>>(wvh, woh, bo, out);
}

// round 11
// speedup vs baseline: 1.1221x; 1.0093x over previous
#include <cuda_runtime.h>
#include <cuda_fp16.h>
#include <math.h>
#include <stdint.h>

#define B_ 4
#define S_ 2048
#define D_ 1024
#define H_ 16
#define HD_ 64
#define M_ (B_*S_)   // 8192

// fp16 scratch
__device__ __half g_qh[(size_t)B_*H_*S_*HD_];
__device__ __half g_kh[(size_t)B_*H_*S_*HD_];
__device__ __half g_vh[(size_t)B_*H_*S_*HD_];
__device__ __half g_xh[(size_t)M_*D_];
__device__ __half g_wvh[(size_t)M_*D_];
__device__ __half g_wt[(size_t)3*H_*HD_*D_];    // [z][h][n=64][k=1024]
__device__ __half g_woh[(size_t)D_*D_];         // [n][k]

// ---------------------------------------------------------------------------
__device__ __forceinline__ uint32_t smem_u32(const void* p) {
    uint32_t a;
    asm("{ .reg .u64 t; cvta.to.shared.u64 t, %1; cvt.u32.u64 %0, t; }" : "=r"(a) : "l"(p));
    return a;
}
__device__ __forceinline__ void cpa16(uint32_t dst, const void* src) {
    asm volatile("cp.async.cg.shared.global [%0], [%1], 16;" :: "r"(dst), "l"(src));
}
__device__ __forceinline__ void cpa_commit() {
    asm volatile("cp.async.commit_group;" ::: "memory");
}
__device__ __forceinline__ float ex2(float x) {
    float r; asm("ex2.approx.ftz.f32 %0, %1;" : "=f"(r) : "f"(x)); return r;
}
__device__ __forceinline__ void mma16816(float c[4], const uint32_t a[4], const uint32_t b[2]) {
    asm volatile("mma.sync.aligned.m16n8k16.row.col.f32.f16.f16.f32 "
                 "{%0,%1,%2,%3}, {%4,%5,%6,%7}, {%8,%9}, {%0,%1,%2,%3};"
                 : "+f"(c[0]), "+f"(c[1]), "+f"(c[2]), "+f"(c[3])
                 : "r"(a[0]), "r"(a[1]), "r"(a[2]), "r"(a[3]), "r"(b[0]), "r"(b[1]));
}

// =================== GEMM (exact R7/R9 config) =============================
#define RS2 144
#define TILE2 (128 * RS2)          // 18432 B
#define STAGE2 (2 * TILE2)         // 36864 B (A+B)
#define GSMEM (3 * STAGE2)         // 110592 B
#define NKT2 16                    // 1024 / 64

__device__ __forceinline__ void load_stage(uint32_t sbase,
                                           const __half* __restrict__ A,
                                           const __half* __restrict__ Bg,
                                           int kt, int tid) {
    const uint32_t sA = sbase, sB = sbase + TILE2;
    #pragma unroll
    for (int i = 0; i < 4; ++i) {
        int idx = tid + i * 256;
        int row = idx >> 3, c = idx & 7;
        const size_t go = (size_t)row * D_ + kt * 64 + c * 8;
        cpa16(sA + row * RS2 + c * 16, A + go);
        cpa16(sB + row * RS2 + c * 16, Bg + go);
    }
}

__device__ __forceinline__ void load_frags(uint32_t sA, uint32_t sB, int ks,
                                           int warp_m, int warp_n, int lane,
                                           uint32_t a[4][4], uint32_t b[4][2]) {
    #pragma unroll
    for (int i = 0; i < 4; ++i) {
        int row = warp_m * 64 + i * 16 + (lane & 15);
        uint32_t addr = sA + row * RS2 + (ks * 16 + (lane >> 4) * 8) * 2;
        asm volatile("ldmatrix.sync.aligned.m8n8.x4.shared.b16 {%0,%1,%2,%3}, [%4];"
                     : "=r"(a[i][0]), "=r"(a[i][1]), "=r"(a[i][2]), "=r"(a[i][3])
                     : "r"(addr));
    }
    #pragma unroll
    for (int jj = 0; jj < 2; ++jj) {
        int g = lane >> 3, lr = lane & 7;
        int n = warp_n * 32 + jj * 16 + (g >> 1) * 8 + lr;
        uint32_t addr = sB + n * RS2 + (ks * 16 + (g & 1) * 8) * 2;
        uint32_t r0, r1, r2, r3;
        asm volatile("ldmatrix.sync.aligned.m8n8.x4.shared.b16 {%0,%1,%2,%3}, [%4];"
                     : "=r"(r0), "=r"(r1), "=r"(r2), "=r"(r3) : "r"(addr));
        b[jj * 2][0] = r0; b[jj * 2][1] = r1;
        b[jj * 2 + 1][0] = r2; b[jj * 2 + 1][1] = r3;
    }
}

__device__ __forceinline__ void do_mmas(const uint32_t a[4][4], const uint32_t b[4][2],
                                        float c[4][4][4]) {
    #pragma unroll
    for (int i = 0; i < 4; ++i)
        #pragma unroll
        for (int j = 0; j < 4; ++j)
            mma16816(c[i][j], a[i], b[j]);
}

__device__ __forceinline__ void gemm_main(uint32_t s, const __half* __restrict__ A,
                                          const __half* __restrict__ Bg,
                                          int tid, int warp_m, int warp_n, int lane,
                                          float c[4][4][4]) {
    load_stage(s + 0 * STAGE2, A, Bg, 0, tid); cpa_commit();
    load_stage(s + 1 * STAGE2, A, Bg, 1, tid); cpa_commit();

    uint32_t af[2][4][4], bf[2][4][2];

    #pragma unroll 1
    for (int kt = 0; kt < NKT2; ++kt) {
        if (kt < NKT2 - 1) asm volatile("cp.async.wait_group 1;" ::: "memory");
        else               asm volatile("cp.async.wait_group 0;" ::: "memory");
        __syncthreads();
        if (kt + 2 < NKT2) {
            load_stage(s + ((kt + 2) % 3) * STAGE2, A, Bg, kt + 2, tid);
            cpa_commit();
        }
        const uint32_t sA = s + (kt % 3) * STAGE2, sB = sA + TILE2;

        load_frags(sA, sB, 0, warp_m, warp_n, lane, af[0], bf[0]);
        #pragma unroll
        for (int ks = 0; ks < 4; ++ks) {
            if (ks < 3)
                load_frags(sA, sB, ks + 1, warp_m, warp_n, lane,
                           af[(ks + 1) & 1], bf[(ks + 1) & 1]);
            do_mmas(af[ks & 1], bf[ks & 1], c);
        }
    }
}

// ---------------------------------------------------------------------------
// QKV projection -> fp16 Q/K/V
// ---------------------------------------------------------------------------
__global__ __launch_bounds__(256, 2) void qkv_mma(
    const __half* __restrict__ Xh, const __half* __restrict__ Wt,
    const float* __restrict__ bq, const float* __restrict__ bk,
    const float* __restrict__ bv) {
    extern __shared__ __align__(16) char sm[];
    const uint32_t s = smem_u32(sm);
    const int tid = threadIdx.x, lane = tid & 31, wid = tid >> 5;
    const int warp_m = wid & 1, warp_n = wid >> 1;
    const int z = blockIdx.z, h0 = blockIdx.x * 2, m0 = blockIdx.y * 128;

    const __half* A  = Xh + (size_t)m0 * D_;
    const __half* Bg = Wt + ((size_t)(z * H_ + h0) * HD_) * D_;
    const float* bias = (z == 0) ? bq : (z == 1) ? bk : bv;
    __half* out       = (z == 0) ? g_qh : (z == 1) ? g_kh : g_vh;

    float c[4][4][4] = {};
    gemm_main(s, A, Bg, tid, warp_m, warp_n, lane, c);

    #pragma unroll
    for (int i = 0; i < 4; ++i) {
        #pragma unroll
        for (int j = 0; j < 4; ++j) {
            const int n = warp_n * 32 + j * 8 + (lane & 3) * 2;
            const int head = h0 + (n >> 6), e = n & 63;
            const float b0 = bias[head * HD_ + e], b1 = bias[head * HD_ + e + 1];
            #pragma unroll
            for (int half_ = 0; half_ < 2; ++half_) {
                const int m = m0 + warp_m * 64 + i * 16 + (lane >> 2) + half_ * 8;
                const int bb = m >> 11, sI = m & 2047;
                __half2 hv = __floats2half2_rn(c[i][j][half_ * 2 + 0] + b0,
                                               c[i][j][half_ * 2 + 1] + b1);
                *(__half2*)(out + (((size_t)(bb * H_ + head) * S_ + sI) * HD_ + e)) = hv;
            }
        }
    }
}

// ---------------------------------------------------------------------------
// Output projection: C = WVh * Woh^T + bo
// ---------------------------------------------------------------------------
__global__ __launch_bounds__(256, 2) void out_mma(
    const __half* __restrict__ WVh, const __half* __restrict__ Woh,
    const float* __restrict__ bo, float* __restrict__ outp) {
    extern __shared__ __align__(16) char sm[];
    const uint32_t s = smem_u32(sm);
    const int tid = threadIdx.x, lane = tid & 31, wid = tid >> 5;
    const int warp_m = wid & 1, warp_n = wid >> 1;
    const int n0 = blockIdx.x * 128, m0 = blockIdx.y * 128;

    const __half* A  = WVh + (size_t)m0 * D_;
    const __half* Bg = Woh + (size_t)n0 * D_;

    float c[4][4][4] = {};
    gemm_main(s, A, Bg, tid, warp_m, warp_n, lane, c);

    #pragma unroll
    for (int i = 0; i < 4; ++i) {
        #pragma unroll
        for (int j = 0; j < 4; ++j) {
            const int n = n0 + warp_n * 32 + j * 8 + (lane & 3) * 2;
            const float b0 = bo[n], b1 = bo[n + 1];
            #pragma unroll
            for (int half_ = 0; half_ < 2; ++half_) {
                const int m = m0 + warp_m * 64 + i * 16 + (lane >> 2) + half_ * 8;
                float2 v;
                v.x = c[i][j][half_ * 2 + 0] + b0;
                v.y = c[i][j][half_ * 2 + 1] + b1;
                *(float2*)(outp + (size_t)m * D_ + n) = v;
            }
        }
    }
}

// ===== attention: fp16x2 exponentials + MMA row-sum softmax =================
#define ARS 144
#define ATILE (64 * ARS)
#define ASTG (2 * ATILE)
#define ASMEM (3 * ASTG)           // 55296 B

__global__ __launch_bounds__(256) void attn_mma() {
    extern __shared__ __align__(16) char sm[];
    const uint32_t s = smem_u32(sm);
    const int tid = threadIdx.x, lane = tid & 31, w = tid >> 5;
    const int bh = blockIdx.y;
    const int q0 = (gridDim.x - 1 - blockIdx.x) * 128;   // heavy tiles first

    const __half* __restrict__ Qb = g_qh + (size_t)bh * S_ * HD_;
    const __half* __restrict__ Kb = g_kh + (size_t)bh * S_ * HD_;
    const __half* __restrict__ Vb = g_vh + (size_t)bh * S_ * HD_;

    const int r0 = q0 + w * 16 + (lane >> 2);
    const int cq = lane & 3;
    const float SC = 0.18033688f;                 // 0.125 * log2(e)
    uint32_t qf[4][4];
    {
        const __half2 sc2 = __floats2half2_rn(SC, SC);
        const __half2* Qr0 = (const __half2*)(Qb + (size_t)r0 * HD_);
        const __half2* Qr1 = (const __half2*)(Qb + (size_t)(r0 + 8) * HD_);
        #pragma unroll
        for (int t = 0; t < 4; ++t) {
            __half2 v0 = __hmul2(Qr0[t * 8 + cq], sc2);
            __half2 v1 = __hmul2(Qr1[t * 8 + cq], sc2);
            __half2 v2 = __hmul2(Qr0[t * 8 + 4 + cq], sc2);
            __half2 v3 = __hmul2(Qr1[t * 8 + 4 + cq], sc2);
            qf[t][0] = *(const uint32_t*)&v0;
            qf[t][1] = *(const uint32_t*)&v1;
            qf[t][2] = *(const uint32_t*)&v2;
            qf[t][3] = *(const uint32_t*)&v3;
        }
    }

    float o[8][4];
    #pragma unroll
    for (int j = 0; j < 8; ++j)
        #pragma unroll
        for (int x = 0; x < 4; ++x) o[j][x] = 0.f;
    float m0 = -INFINITY, m1 = -INFINITY, l0 = 0.f, l1 = 0.f;

    const int NT = (q0 + 128) / 64;

    auto load_tile = [&](int kt, int stg) {
        const uint32_t base = s + stg * ASTG;
        #pragma unroll
        for (int i = 0; i < 2; ++i) {
            int idx = tid + i * 256;
            int row = idx >> 3, c = idx & 7;
            const size_t go = (size_t)(kt * 64 + row) * HD_ + c * 8;
            cpa16(base + row * ARS + c * 16, Kb + go);
            cpa16(base + ATILE + row * ARS + c * 16, Vb + go);
        }
    };

    load_tile(0, 0); cpa_commit();
    if (NT > 1) { load_tile(1, 1); cpa_commit(); }

    const int g = lane >> 3, lr = lane & 7;
    const uint32_t ONES2 = 0x3C003C00u;           // {1.0h, 1.0h}
    uint32_t onesb[2] = {ONES2, ONES2};

    #pragma unroll 1
    for (int kt = 0; kt < NT; ++kt) {
        const int k0 = kt * 64;
        if (kt < NT - 1) asm volatile("cp.async.wait_group 1;" ::: "memory");
        else             asm volatile("cp.async.wait_group 0;" ::: "memory");
        __syncthreads();
        if (kt + 2 < NT) { load_tile(kt + 2, (kt + 2) % 3); cpa_commit(); }

        const uint32_t sK = s + (kt % 3) * ASTG, sV = sK + ATILE;

        // ---- S = (Q*sc) K^T ----
        float sa[8][4];
        #pragma unroll
        for (int j = 0; j < 8; ++j)
            #pragma unroll
            for (int x = 0; x < 4; ++x) sa[j][x] = 0.f;
        #pragma unroll
        for (int t = 0; t < 4; ++t) {
            uint32_t kb[8][2];
            #pragma unroll
            for (int jp = 0; jp < 4; ++jp) {
                const int n = jp * 16 + (g >> 1) * 8 + lr;
                uint32_t addr = sK + n * ARS + t * 32 + (g & 1) * 16;
                uint32_t r0_, r1_, r2_, r3_;
                asm volatile("ldmatrix.sync.aligned.m8n8.x4.shared.b16 {%0,%1,%2,%3}, [%4];"
                             : "=r"(r0_), "=r"(r1_), "=r"(r2_), "=r"(r3_) : "r"(addr));
                kb[jp * 2][0] = r0_; kb[jp * 2][1] = r1_;
                kb[jp * 2 + 1][0] = r2_; kb[jp * 2 + 1][1] = r3_;
            }
            #pragma unroll
            for (int j = 0; j < 8; ++j)
                mma16816(sa[j], qf[t], kb[j]);
        }

        // ---- mask + running-max ----
        const bool needmask = (k0 + 63 > r0);
        float tm0 = -INFINITY, tm1 = -INFINITY;
        #pragma unroll
        for (int j = 0; j < 8; ++j) {
            if (needmask) {
                const int col = k0 + j * 8 + (lane & 3) * 2;
                if (col > r0)         sa[j][0] = -INFINITY;
                if (col + 1 > r0)     sa[j][1] = -INFINITY;
                if (col > r0 + 8)     sa[j][2] = -INFINITY;
                if (col + 1 > r0 + 8) sa[j][3] = -INFINITY;
            }
            tm0 = fmaxf(tm0, fmaxf(sa[j][0], sa[j][1]));
            tm1 = fmaxf(tm1, fmaxf(sa[j][2], sa[j][3]));
        }
        tm0 = fmaxf(tm0, __shfl_xor_sync(0xffffffffu, tm0, 1));
        tm0 = fmaxf(tm0, __shfl_xor_sync(0xffffffffu, tm0, 2));
        tm1 = fmaxf(tm1, __shfl_xor_sync(0xffffffffu, tm1, 1));
        tm1 = fmaxf(tm1, __shfl_xor_sync(0xffffffffu, tm1, 2));

        const float mn0 = fmaxf(m0, tm0), mn1 = fmaxf(m1, tm1);
        const float c0 = ex2(m0 - mn0), c1 = ex2(m1 - mn1);
        m0 = mn0; m1 = mn1;

        // ---- P = exp2(S - m) computed directly in fp16x2 ----
        uint32_t pa[4][4];
        #pragma unroll
        for (int j = 0; j < 8; ++j) {
            const float a0 = sa[j][0] - mn0, a1 = sa[j][1] - mn0;
            const float a2 = sa[j][2] - mn1, a3 = sa[j][3] - mn1;
            uint32_t h01, h23;
            asm("cvt.rn.f16x2.f32 %0, %1, %2;" : "=r"(h01) : "f"(a1), "f"(a0));
            asm("cvt.rn.f16x2.f32 %0, %1, %2;" : "=r"(h23) : "f"(a3), "f"(a2));
            asm("ex2.approx.f16x2 %0, %1;" : "=r"(h01) : "r"(h01));
            asm("ex2.approx.f16x2 %0, %1;" : "=r"(h23) : "r"(h23));
            const int t = j >> 1;
            if ((j & 1) == 0) { pa[t][0] = h01; pa[t][1] = h23; }
            else              { pa[t][2] = h01; pa[t][3] = h23; }
        }

        // ---- rescale O ----
        #pragma unroll
        for (int j = 0; j < 8; ++j) {
            o[j][0] *= c0; o[j][1] *= c0;
            o[j][2] *= c1; o[j][3] *= c1;
        }

        // ---- O += P V, and row sums ls = P * ones via MMA ----
        float ls[4] = {0.f, 0.f, 0.f, 0.f};
        #pragma unroll
        for (int t = 0; t < 4; ++t) {
            uint32_t vb[8][2];
            #pragma unroll
            for (int jp = 0; jp < 4; ++jp) {
                const int row = t * 16 + (g & 1) * 8 + lr;
                uint32_t addr = sV + row * ARS + jp * 32 + (g >> 1) * 16;
                uint32_t r0_, r1_, r2_, r3_;
                asm volatile("ldmatrix.sync.aligned.m8n8.x4.trans.shared.b16 {%0,%1,%2,%3}, [%4];"
                             : "=r"(r0_), "=r"(r1_), "=r"(r2_), "=r"(r3_) : "r"(addr));
                vb[jp * 2][0] = r0_; vb[jp * 2][1] = r1_;
                vb[jp * 2 + 1][0] = r2_; vb[jp * 2 + 1][1] = r3_;
            }
            mma16816(ls, pa[t], onesb);
            #pragma unroll
            for (int j = 0; j < 8; ++j)
                mma16816(o[j], pa[t], vb[j]);
        }

        l0 = l0 * c0 + ls[0];
        l1 = l1 * c1 + ls[2];
    }

    // ---- epilogue ----
    const float i0 = 1.f / l0, i1 = 1.f / l1;
    const int b = bh >> 4, h = bh & 15;
    __half* out0 = g_wvh + ((size_t)(b * S_) + r0) * D_ + h * HD_ + (lane & 3) * 2;
    __half* out1 = g_wvh + ((size_t)(b * S_) + r0 + 8) * D_ + h * HD_ + (lane & 3) * 2;
    #pragma unroll
    for (int j = 0; j < 8; ++j) {
        *(__half2*)(out0 + j * 8) = __floats2half2_rn(o[j][0] * i0, o[j][1] * i0);
        *(__half2*)(out1 + j * 8) = __floats2half2_rn(o[j][2] * i1, o[j][3] * i1);
    }
}

// ---------------------------------------------------------------------------
// fused prep: cvt X (blocks 0..8191), cvt Wo (8192..9215), wtrans (9216..12287)
// ---------------------------------------------------------------------------
#define NB_X  8192
#define NB_WO 1024
#define NB_WT 3072

__global__ __launch_bounds__(256) void prep(
    const float* __restrict__ X,  const float* __restrict__ Wo,
    const float* __restrict__ Wq, const float* __restrict__ Wk,
    const float* __restrict__ Wv) {
    __shared__ float t[32][33];
    const int b = blockIdx.x, tid = threadIdx.x;

    if (b < NB_X) {
        const int i = (b * 256 + tid) * 4;
        float4 v = *(const float4*)(X + i);
        __half2* o = (__half2*)(g_xh + i);
        o[0] = __floats2half2_rn(v.x, v.y);
        o[1] = __floats2half2_rn(v.z, v.w);
    } else if (b < NB_X + NB_WO) {
        const int i = ((b - NB_X) * 256 + tid) * 4;
        float4 v = *(const float4*)(Wo + i);
        __half2* o = (__half2*)(g_woh + i);
        o[0] = __floats2half2_rn(v.x, v.y);
        o[1] = __floats2half2_rn(v.z, v.w);
    } else {
        const int id = b - NB_X - NB_WO;
        const int bx = id & 1, by = (id >> 1) & 31, bz = id >> 6;
        const int z = bz >> 4, h = bz & 15;
        const float* W = ((z == 0) ? Wq : (z == 1) ? Wk : Wv) + (size_t)h * D_ * HD_;
        __half* out = g_wt + (size_t)bz * HD_ * D_;
        const int n0 = bx * 32, k0 = by * 32;
        const int tx = tid & 31, ty = tid >> 5;
        #pragma unroll
        for (int i = 0; i < 32; i += 8)
            t[ty + i][tx] = W[(size_t)(k0 + ty + i) * HD_ + n0 + tx];
        __syncthreads();
        #pragma unroll
        for (int i = 0; i < 32; i += 8)
            out[(size_t)(n0 + ty + i) * D_ + k0 + tx] = __float2half_rn(t[tx][ty + i]);
    }
}

// ---------------------------------------------------------------------------
extern "C" void kernel_launch(void* const* d_in, const int* in_sizes, int n_in,
                              void* d_out, int out_size) {
    const float* X  = (const float*)d_in[0];
    const float* Wq = (const float*)d_in[1];
    const float* bq = (const float*)d_in[2];
    const float* Wk = (const float*)d_in[3];
    const float* bk = (const float*)d_in[4];
    const float* Wv = (const float*)d_in[5];
    const float* bv = (const float*)d_in[6];
    const float* Wo = (const float*)d_in[7];
    const float* bo = (const float*)d_in[8];
    float* out = (float*)d_out;

    cudaFuncSetAttribute(qkv_mma, cudaFuncAttributeMaxDynamicSharedMemorySize, GSMEM);
    cudaFuncSetAttribute(out_mma, cudaFuncAttributeMaxDynamicSharedMemorySize, GSMEM);
    cudaFuncSetAttribute(attn_mma, cudaFuncAttributeMaxDynamicSharedMemorySize, ASMEM);

    __half* xh  = nullptr; cudaGetSymbolAddress((void**)&xh,  g_xh);
    __half* wvh = nullptr; cudaGetSymbolAddress((void**)&wvh, g_wvh);
    __half* wt  = nullptr; cudaGetSymbolAddress((void**)&wt,  g_wt);
    __half* woh = nullptr; cudaGetSymbolAddress((void**)&woh, g_woh);

    prep<<<NB_X + NB_WO + NB_WT, 256>>>(X, Wo, Wq, Wk, Wv);
    qkv_mma<<<dim3(H_ / 2, M_ / 128, 3), 256, GSMEM>>>(xh, wt, bq, bk, bv);
    attn_mma<<<dim3(S_ / 128, B_ * H_), 256, ASMEM>>>();
    out_mma<<<dim3(D_ / 128, M_ / 128), 256, GSMEM>>>(wvh, woh, bo, out);
}

// round 12
// speedup vs baseline: 1.1327x; 1.0094x over previous
#include <cuda_runtime.h>
#include <cuda_fp16.h>
#include <math.h>
#include <stdint.h>

#define B_ 4
#define S_ 2048
#define D_ 1024
#define H_ 16
#define HD_ 64
#define M_ (B_*S_)   // 8192

// fp16 scratch
__device__ __half g_qh[(size_t)B_*H_*S_*HD_];
__device__ __half g_kh[(size_t)B_*H_*S_*HD_];
__device__ __half g_vh[(size_t)B_*H_*S_*HD_];
__device__ __half g_xh[(size_t)M_*D_];
__device__ __half g_wvh[(size_t)M_*D_];
__device__ __half g_wt[(size_t)3*H_*HD_*D_];    // [z][h][n=64][k=1024]
__device__ __half g_woh[(size_t)D_*D_];         // [n][k]

// ---------------------------------------------------------------------------
__device__ __forceinline__ uint32_t smem_u32(const void* p) {
    uint32_t a;
    asm("{ .reg .u64 t; cvta.to.shared.u64 t, %1; cvt.u32.u64 %0, t; }" : "=r"(a) : "l"(p));
    return a;
}
__device__ __forceinline__ void cpa16(uint32_t dst, const void* src) {
    asm volatile("cp.async.cg.shared.global [%0], [%1], 16;" :: "r"(dst), "l"(src));
}
__device__ __forceinline__ void cpa_commit() {
    asm volatile("cp.async.commit_group;" ::: "memory");
}
__device__ __forceinline__ float ex2(float x) {
    float r; asm("ex2.approx.ftz.f32 %0, %1;" : "=f"(r) : "f"(x)); return r;
}
__device__ __forceinline__ void mma16816(float c[4], const uint32_t a[4], const uint32_t b[2]) {
    asm volatile("mma.sync.aligned.m16n8k16.row.col.f32.f16.f16.f32 "
                 "{%0,%1,%2,%3}, {%4,%5,%6,%7}, {%8,%9}, {%0,%1,%2,%3};"
                 : "+f"(c[0]), "+f"(c[1]), "+f"(c[2]), "+f"(c[3])
                 : "r"(a[0]), "r"(a[1]), "r"(a[2]), "r"(a[3]), "r"(b[0]), "r"(b[1]));
}

// =================== GEMM: R7 tiles + interleaved frag scheduling ===========
#define RS2 144
#define TILE2 (128 * RS2)          // 18432 B
#define STAGE2 (2 * TILE2)         // 36864 B (A+B)
#define GSMEM (3 * STAGE2)         // 110592 B
#define NKT2 16                    // 1024 / 64

__device__ __forceinline__ void load_stage(uint32_t sbase,
                                           const __half* __restrict__ A,
                                           const __half* __restrict__ Bg,
                                           int kt, int tid) {
    const uint32_t sA = sbase, sB = sbase + TILE2;
    #pragma unroll
    for (int i = 0; i < 4; ++i) {
        int idx = tid + i * 256;
        int row = idx >> 3, c = idx & 7;
        const size_t go = (size_t)row * D_ + kt * 64 + c * 8;
        cpa16(sA + row * RS2 + c * 16, A + go);
        cpa16(sB + row * RS2 + c * 16, Bg + go);
    }
}

// one A fragment row-block (i-th 16 rows of this warp's 64)
__device__ __forceinline__ void load_frag_a(uint32_t sA, int ks, int warp_m, int lane,
                                            int i, uint32_t a[4]) {
    int row = warp_m * 64 + i * 16 + (lane & 15);
    uint32_t addr = sA + row * RS2 + (ks * 16 + (lane >> 4) * 8) * 2;
    asm volatile("ldmatrix.sync.aligned.m8n8.x4.shared.b16 {%0,%1,%2,%3}, [%4];"
                 : "=r"(a[0]), "=r"(a[1]), "=r"(a[2]), "=r"(a[3]) : "r"(addr));
}

// one B pair (jj covers 2 n-blocks) via x4
__device__ __forceinline__ void load_frag_b(uint32_t sB, int ks, int warp_n, int lane,
                                            int jj, uint32_t b0[2], uint32_t b1[2]) {
    int g = lane >> 3, lr = lane & 7;
    int n = warp_n * 32 + jj * 16 + (g >> 1) * 8 + lr;
    uint32_t addr = sB + n * RS2 + (ks * 16 + (g & 1) * 8) * 2;
    uint32_t r0, r1, r2, r3;
    asm volatile("ldmatrix.sync.aligned.m8n8.x4.shared.b16 {%0,%1,%2,%3}, [%4];"
                 : "=r"(r0), "=r"(r1), "=r"(r2), "=r"(r3) : "r"(addr));
    b0[0] = r0; b0[1] = r1;
    b1[0] = r2; b1[1] = r3;
}

__device__ __forceinline__ void gemm_main(uint32_t s, const __half* __restrict__ A,
                                          const __half* __restrict__ Bg,
                                          int tid, int warp_m, int warp_n, int lane,
                                          float c[4][4][4]) {
    load_stage(s + 0 * STAGE2, A, Bg, 0, tid); cpa_commit();
    load_stage(s + 1 * STAGE2, A, Bg, 1, tid); cpa_commit();

    uint32_t af[2][4][4], bf[2][4][2];

    #pragma unroll 1
    for (int kt = 0; kt < NKT2; ++kt) {
        if (kt < NKT2 - 1) asm volatile("cp.async.wait_group 1;" ::: "memory");
        else               asm volatile("cp.async.wait_group 0;" ::: "memory");
        __syncthreads();
        const uint32_t sA = s + (kt % 3) * STAGE2, sB = sA + TILE2;

        // initial frag set for ks=0 (6 LDSM burst — minimum possible)
        #pragma unroll
        for (int i = 0; i < 4; ++i) load_frag_a(sA, 0, warp_m, lane, i, af[0][i]);
        load_frag_b(sB, 0, warp_n, lane, 0, bf[0][0], bf[0][1]);
        load_frag_b(sB, 0, warp_n, lane, 1, bf[0][2], bf[0][3]);

        if (kt + 2 < NKT2) {
            load_stage(s + ((kt + 2) % 3) * STAGE2, A, Bg, kt + 2, tid);
            cpa_commit();
        }

        // interleaved: next-ks LDSMs spread between MMA groups
        #pragma unroll
        for (int ks = 0; ks < 4; ++ks) {
            const int cur = ks & 1, nxt = cur ^ 1;
            const bool pf = (ks < 3);
            #pragma unroll
            for (int j = 0; j < 4; ++j) mma16816(c[0][j], af[cur][0], bf[cur][j]);
            if (pf) {
                load_frag_a(sA, ks + 1, warp_m, lane, 0, af[nxt][0]);
                load_frag_a(sA, ks + 1, warp_m, lane, 1, af[nxt][1]);
            }
            #pragma unroll
            for (int j = 0; j < 4; ++j) mma16816(c[1][j], af[cur][1], bf[cur][j]);
            if (pf) {
                load_frag_a(sA, ks + 1, warp_m, lane, 2, af[nxt][2]);
                load_frag_a(sA, ks + 1, warp_m, lane, 3, af[nxt][3]);
            }
            #pragma unroll
            for (int j = 0; j < 4; ++j) mma16816(c[2][j], af[cur][2], bf[cur][j]);
            if (pf) {
                load_frag_b(sB, ks + 1, warp_n, lane, 0, bf[nxt][0], bf[nxt][1]);
                load_frag_b(sB, ks + 1, warp_n, lane, 1, bf[nxt][2], bf[nxt][3]);
            }
            #pragma unroll
            for (int j = 0; j < 4; ++j) mma16816(c[3][j], af[cur][3], bf[cur][j]);
        }
    }
}

// ---------------------------------------------------------------------------
// QKV projection -> fp16 Q/K/V
// ---------------------------------------------------------------------------
__global__ __launch_bounds__(256, 2) void qkv_mma(
    const __half* __restrict__ Xh, const __half* __restrict__ Wt,
    const float* __restrict__ bq, const float* __restrict__ bk,
    const float* __restrict__ bv) {
    extern __shared__ __align__(16) char sm[];
    const uint32_t s = smem_u32(sm);
    const int tid = threadIdx.x, lane = tid & 31, wid = tid >> 5;
    const int warp_m = wid & 1, warp_n = wid >> 1;
    const int z = blockIdx.z, h0 = blockIdx.x * 2, m0 = blockIdx.y * 128;

    const __half* A  = Xh + (size_t)m0 * D_;
    const __half* Bg = Wt + ((size_t)(z * H_ + h0) * HD_) * D_;
    const float* bias = (z == 0) ? bq : (z == 1) ? bk : bv;
    __half* out       = (z == 0) ? g_qh : (z == 1) ? g_kh : g_vh;

    float c[4][4][4] = {};
    gemm_main(s, A, Bg, tid, warp_m, warp_n, lane, c);

    #pragma unroll
    for (int i = 0; i < 4; ++i) {
        #pragma unroll
        for (int j = 0; j < 4; ++j) {
            const int n = warp_n * 32 + j * 8 + (lane & 3) * 2;
            const int head = h0 + (n >> 6), e = n & 63;
            const float b0 = bias[head * HD_ + e], b1 = bias[head * HD_ + e + 1];
            #pragma unroll
            for (int half_ = 0; half_ < 2; ++half_) {
                const int m = m0 + warp_m * 64 + i * 16 + (lane >> 2) + half_ * 8;
                const int bb = m >> 11, sI = m & 2047;
                __half2 hv = __floats2half2_rn(c[i][j][half_ * 2 + 0] + b0,
                                               c[i][j][half_ * 2 + 1] + b1);
                *(__half2*)(out + (((size_t)(bb * H_ + head) * S_ + sI) * HD_ + e)) = hv;
            }
        }
    }
}

// ---------------------------------------------------------------------------
// Output projection: C = WVh * Woh^T + bo
// ---------------------------------------------------------------------------
__global__ __launch_bounds__(256, 2) void out_mma(
    const __half* __restrict__ WVh, const __half* __restrict__ Woh,
    const float* __restrict__ bo, float* __restrict__ outp) {
    extern __shared__ __align__(16) char sm[];
    const uint32_t s = smem_u32(sm);
    const int tid = threadIdx.x, lane = tid & 31, wid = tid >> 5;
    const int warp_m = wid & 1, warp_n = wid >> 1;
    const int n0 = blockIdx.x * 128, m0 = blockIdx.y * 128;

    const __half* A  = WVh + (size_t)m0 * D_;
    const __half* Bg = Woh + (size_t)n0 * D_;

    float c[4][4][4] = {};
    gemm_main(s, A, Bg, tid, warp_m, warp_n, lane, c);

    #pragma unroll
    for (int i = 0; i < 4; ++i) {
        #pragma unroll
        for (int j = 0; j < 4; ++j) {
            const int n = n0 + warp_n * 32 + j * 8 + (lane & 3) * 2;
            const float b0 = bo[n], b1 = bo[n + 1];
            #pragma unroll
            for (int half_ = 0; half_ < 2; ++half_) {
                const int m = m0 + warp_m * 64 + i * 16 + (lane >> 2) + half_ * 8;
                float2 v;
                v.x = c[i][j][half_ * 2 + 0] + b0;
                v.y = c[i][j][half_ * 2 + 1] + b1;
                *(float2*)(outp + (size_t)m * D_ + n) = v;
            }
        }
    }
}

// ===== attention (R11: fp16x2 exp + MMA row-sum) ============================
#define ARS 144
#define ATILE (64 * ARS)
#define ASTG (2 * ATILE)
#define ASMEM (3 * ASTG)           // 55296 B

__global__ __launch_bounds__(256) void attn_mma() {
    extern __shared__ __align__(16) char sm[];
    const uint32_t s = smem_u32(sm);
    const int tid = threadIdx.x, lane = tid & 31, w = tid >> 5;
    const int bh = blockIdx.y;
    const int q0 = (gridDim.x - 1 - blockIdx.x) * 128;   // heavy tiles first

    const __half* __restrict__ Qb = g_qh + (size_t)bh * S_ * HD_;
    const __half* __restrict__ Kb = g_kh + (size_t)bh * S_ * HD_;
    const __half* __restrict__ Vb = g_vh + (size_t)bh * S_ * HD_;

    const int r0 = q0 + w * 16 + (lane >> 2);
    const int cq = lane & 3;
    const float SC = 0.18033688f;                 // 0.125 * log2(e)
    uint32_t qf[4][4];
    {
        const __half2 sc2 = __floats2half2_rn(SC, SC);
        const __half2* Qr0 = (const __half2*)(Qb + (size_t)r0 * HD_);
        const __half2* Qr1 = (const __half2*)(Qb + (size_t)(r0 + 8) * HD_);
        #pragma unroll
        for (int t = 0; t < 4; ++t) {
            __half2 v0 = __hmul2(Qr0[t * 8 + cq], sc2);
            __half2 v1 = __hmul2(Qr1[t * 8 + cq], sc2);
            __half2 v2 = __hmul2(Qr0[t * 8 + 4 + cq], sc2);
            __half2 v3 = __hmul2(Qr1[t * 8 + 4 + cq], sc2);
            qf[t][0] = *(const uint32_t*)&v0;
            qf[t][1] = *(const uint32_t*)&v1;
            qf[t][2] = *(const uint32_t*)&v2;
            qf[t][3] = *(const uint32_t*)&v3;
        }
    }

    float o[8][4];
    #pragma unroll
    for (int j = 0; j < 8; ++j)
        #pragma unroll
        for (int x = 0; x < 4; ++x) o[j][x] = 0.f;
    float m0 = -INFINITY, m1 = -INFINITY, l0 = 0.f, l1 = 0.f;

    const int NT = (q0 + 128) / 64;

    auto load_tile = [&](int kt, int stg) {
        const uint32_t base = s + stg * ASTG;
        #pragma unroll
        for (int i = 0; i < 2; ++i) {
            int idx = tid + i * 256;
            int row = idx >> 3, c = idx & 7;
            const size_t go = (size_t)(kt * 64 + row) * HD_ + c * 8;
            cpa16(base + row * ARS + c * 16, Kb + go);
            cpa16(base + ATILE + row * ARS + c * 16, Vb + go);
        }
    };

    load_tile(0, 0); cpa_commit();
    if (NT > 1) { load_tile(1, 1); cpa_commit(); }

    const int g = lane >> 3, lr = lane & 7;
    const uint32_t ONES2 = 0x3C003C00u;           // {1.0h, 1.0h}
    uint32_t onesb[2] = {ONES2, ONES2};

    #pragma unroll 1
    for (int kt = 0; kt < NT; ++kt) {
        const int k0 = kt * 64;
        if (kt < NT - 1) asm volatile("cp.async.wait_group 1;" ::: "memory");
        else             asm volatile("cp.async.wait_group 0;" ::: "memory");
        __syncthreads();
        if (kt + 2 < NT) { load_tile(kt + 2, (kt + 2) % 3); cpa_commit(); }

        const uint32_t sK = s + (kt % 3) * ASTG, sV = sK + ATILE;

        // ---- S = (Q*sc) K^T ----
        float sa[8][4];
        #pragma unroll
        for (int j = 0; j < 8; ++j)
            #pragma unroll
            for (int x = 0; x < 4; ++x) sa[j][x] = 0.f;
        #pragma unroll
        for (int t = 0; t < 4; ++t) {
            uint32_t kb[8][2];
            #pragma unroll
            for (int jp = 0; jp < 4; ++jp) {
                const int n = jp * 16 + (g >> 1) * 8 + lr;
                uint32_t addr = sK + n * ARS + t * 32 + (g & 1) * 16;
                uint32_t r0_, r1_, r2_, r3_;
                asm volatile("ldmatrix.sync.aligned.m8n8.x4.shared.b16 {%0,%1,%2,%3}, [%4];"
                             : "=r"(r0_), "=r"(r1_), "=r"(r2_), "=r"(r3_) : "r"(addr));
                kb[jp * 2][0] = r0_; kb[jp * 2][1] = r1_;
                kb[jp * 2 + 1][0] = r2_; kb[jp * 2 + 1][1] = r3_;
            }
            #pragma unroll
            for (int j = 0; j < 8; ++j)
                mma16816(sa[j], qf[t], kb[j]);
        }

        // ---- mask + running-max ----
        const bool needmask = (k0 + 63 > r0);
        float tm0 = -INFINITY, tm1 = -INFINITY;
        #pragma unroll
        for (int j = 0; j < 8; ++j) {
            if (needmask) {
                const int col = k0 + j * 8 + (lane & 3) * 2;
                if (col > r0)         sa[j][0] = -INFINITY;
                if (col + 1 > r0)     sa[j][1] = -INFINITY;
                if (col > r0 + 8)     sa[j][2] = -INFINITY;
                if (col + 1 > r0 + 8) sa[j][3] = -INFINITY;
            }
            tm0 = fmaxf(tm0, fmaxf(sa[j][0], sa[j][1]));
            tm1 = fmaxf(tm1, fmaxf(sa[j][2], sa[j][3]));
        }
        tm0 = fmaxf(tm0, __shfl_xor_sync(0xffffffffu, tm0, 1));
        tm0 = fmaxf(tm0, __shfl_xor_sync(0xffffffffu, tm0, 2));
        tm1 = fmaxf(tm1, __shfl_xor_sync(0xffffffffu, tm1, 1));
        tm1 = fmaxf(tm1, __shfl_xor_sync(0xffffffffu, tm1, 2));

        const float mn0 = fmaxf(m0, tm0), mn1 = fmaxf(m1, tm1);
        const float c0 = ex2(m0 - mn0), c1 = ex2(m1 - mn1);
        m0 = mn0; m1 = mn1;

        // ---- P = exp2(S - m) in fp16x2 ----
        uint32_t pa[4][4];
        #pragma unroll
        for (int j = 0; j < 8; ++j) {
            const float a0 = sa[j][0] - mn0, a1 = sa[j][1] - mn0;
            const float a2 = sa[j][2] - mn1, a3 = sa[j][3] - mn1;
            uint32_t h01, h23;
            asm("cvt.rn.f16x2.f32 %0, %1, %2;" : "=r"(h01) : "f"(a1), "f"(a0));
            asm("cvt.rn.f16x2.f32 %0, %1, %2;" : "=r"(h23) : "f"(a3), "f"(a2));
            asm("ex2.approx.f16x2 %0, %1;" : "=r"(h01) : "r"(h01));
            asm("ex2.approx.f16x2 %0, %1;" : "=r"(h23) : "r"(h23));
            const int t = j >> 1;
            if ((j & 1) == 0) { pa[t][0] = h01; pa[t][1] = h23; }
            else              { pa[t][2] = h01; pa[t][3] = h23; }
        }

        // ---- rescale O ----
        #pragma unroll
        for (int j = 0; j < 8; ++j) {
            o[j][0] *= c0; o[j][1] *= c0;
            o[j][2] *= c1; o[j][3] *= c1;
        }

        // ---- O += P V, row sums via MMA ----
        float ls[4] = {0.f, 0.f, 0.f, 0.f};
        #pragma unroll
        for (int t = 0; t < 4; ++t) {
            uint32_t vb[8][2];
            #pragma unroll
            for (int jp = 0; jp < 4; ++jp) {
                const int row = t * 16 + (g & 1) * 8 + lr;
                uint32_t addr = sV + row * ARS + jp * 32 + (g >> 1) * 16;
                uint32_t r0_, r1_, r2_, r3_;
                asm volatile("ldmatrix.sync.aligned.m8n8.x4.trans.shared.b16 {%0,%1,%2,%3}, [%4];"
                             : "=r"(r0_), "=r"(r1_), "=r"(r2_), "=r"(r3_) : "r"(addr));
                vb[jp * 2][0] = r0_; vb[jp * 2][1] = r1_;
                vb[jp * 2 + 1][0] = r2_; vb[jp * 2 + 1][1] = r3_;
            }
            mma16816(ls, pa[t], onesb);
            #pragma unroll
            for (int j = 0; j < 8; ++j)
                mma16816(o[j], pa[t], vb[j]);
        }

        l0 = l0 * c0 + ls[0];
        l1 = l1 * c1 + ls[2];
    }

    // ---- epilogue ----
    const float i0 = 1.f / l0, i1 = 1.f / l1;
    const int b = bh >> 4, h = bh & 15;
    __half* out0 = g_wvh + ((size_t)(b * S_) + r0) * D_ + h * HD_ + (lane & 3) * 2;
    __half* out1 = g_wvh + ((size_t)(b * S_) + r0 + 8) * D_ + h * HD_ + (lane & 3) * 2;
    #pragma unroll
    for (int j = 0; j < 8; ++j) {
        *(__half2*)(out0 + j * 8) = __floats2half2_rn(o[j][0] * i0, o[j][1] * i0);
        *(__half2*)(out1 + j * 8) = __floats2half2_rn(o[j][2] * i1, o[j][3] * i1);
    }
}

// ---------------------------------------------------------------------------
// fused prep: cvt X (blocks 0..8191), cvt Wo (8192..9215), wtrans (9216..12287)
// ---------------------------------------------------------------------------
#define NB_X  8192
#define NB_WO 1024
#define NB_WT 3072

__global__ __launch_bounds__(256) void prep(
    const float* __restrict__ X,  const float* __restrict__ Wo,
    const float* __restrict__ Wq, const float* __restrict__ Wk,
    const float* __restrict__ Wv) {
    __shared__ float t[32][33];
    const int b = blockIdx.x, tid = threadIdx.x;

    if (b < NB_X) {
        const int i = (b * 256 + tid) * 4;
        float4 v = *(const float4*)(X + i);
        __half2* o = (__half2*)(g_xh + i);
        o[0] = __floats2half2_rn(v.x, v.y);
        o[1] = __floats2half2_rn(v.z, v.w);
    } else if (b < NB_X + NB_WO) {
        const int i = ((b - NB_X) * 256 + tid) * 4;
        float4 v = *(const float4*)(Wo + i);
        __half2* o = (__half2*)(g_woh + i);
        o[0] = __floats2half2_rn(v.x, v.y);
        o[1] = __floats2half2_rn(v.z, v.w);
    } else {
        const int id = b - NB_X - NB_WO;
        const int bx = id & 1, by = (id >> 1) & 31, bz = id >> 6;
        const int z = bz >> 4, h = bz & 15;
        const float* W = ((z == 0) ? Wq : (z == 1) ? Wk : Wv) + (size_t)h * D_ * HD_;
        __half* out = g_wt + (size_t)bz * HD_ * D_;
        const int n0 = bx * 32, k0 = by * 32;
        const int tx = tid & 31, ty = tid >> 5;
        #pragma unroll
        for (int i = 0; i < 32; i += 8)
            t[ty + i][tx] = W[(size_t)(k0 + ty + i) * HD_ + n0 + tx];
        __syncthreads();
        #pragma unroll
        for (int i = 0; i < 32; i += 8)
            out[(size_t)(n0 + ty + i) * D_ + k0 + tx] = __float2half_rn(t[tx][ty + i]);
    }
}

// ---------------------------------------------------------------------------
extern "C" void kernel_launch(void* const* d_in, const int* in_sizes, int n_in,
                              void* d_out, int out_size) {
    const float* X  = (const float*)d_in[0];
    const float* Wq = (const float*)d_in[1];
    const float* bq = (const float*)d_in[2];
    const float* Wk = (const float*)d_in[3];
    const float* bk = (const float*)d_in[4];
    const float* Wv = (const float*)d_in[5];
    const float* bv = (const float*)d_in[6];
    const float* Wo = (const float*)d_in[7];
    const float* bo = (const float*)d_in[8];
    float* out = (float*)d_out;

    cudaFuncSetAttribute(qkv_mma, cudaFuncAttributeMaxDynamicSharedMemorySize, GSMEM);
    cudaFuncSetAttribute(out_mma, cudaFuncAttributeMaxDynamicSharedMemorySize, GSMEM);
    cudaFuncSetAttribute(attn_mma, cudaFuncAttributeMaxDynamicSharedMemorySize, ASMEM);

    __half* xh  = nullptr; cudaGetSymbolAddress((void**)&xh,  g_xh);
    __half* wvh = nullptr; cudaGetSymbolAddress((void**)&wvh, g_wvh);
    __half* wt  = nullptr; cudaGetSymbolAddress((void**)&wt,  g_wt);
    __half* woh = nullptr; cudaGetSymbolAddress((void**)&woh, g_woh);

    prep<<<NB_X + NB_WO + NB_WT, 256>>>(X, Wo, Wq, Wk, Wv);
    qkv_mma<<<dim3(H_ / 2, M_ / 128, 3), 256, GSMEM>>>(xh, wt, bq, bk, bv);
    attn_mma<<<dim3(S_ / 128, B_ * H_), 256, ASMEM>>>();
    out_mma<<<dim3(D_ / 128, M_ / 128), 256, GSMEM>>>(wvh, woh, bo, out);
}

// round 13
// speedup vs baseline: 1.1386x; 1.0053x over previous
#include <cuda_runtime.h>
#include <cuda_fp16.h>
#include <math.h>
#include <stdint.h>

#define B_ 4
#define S_ 2048
#define D_ 1024
#define H_ 16
#define HD_ 64
#define M_ (B_*S_)   // 8192

// fp16 scratch
__device__ __half g_qh[(size_t)B_*H_*S_*HD_];
__device__ __half g_kh[(size_t)B_*H_*S_*HD_];
__device__ __half g_vh[(size_t)B_*H_*S_*HD_];
__device__ __half g_xh[(size_t)M_*D_];
__device__ __half g_wvh[(size_t)M_*D_];
__device__ __half g_wt[(size_t)3*H_*HD_*D_];    // [z][h][n=64][k=1024]
__device__ __half g_woh[(size_t)D_*D_];         // [n][k]

// ---------------------------------------------------------------------------
__device__ __forceinline__ uint32_t smem_u32(const void* p) {
    uint32_t a;
    asm("{ .reg .u64 t; cvta.to.shared.u64 t, %1; cvt.u32.u64 %0, t; }" : "=r"(a) : "l"(p));
    return a;
}
__device__ __forceinline__ void cpa16(uint32_t dst, const void* src) {
    asm volatile("cp.async.cg.shared.global [%0], [%1], 16;" :: "r"(dst), "l"(src));
}
__device__ __forceinline__ void cpa_commit() {
    asm volatile("cp.async.commit_group;" ::: "memory");
}
__device__ __forceinline__ float ex2(float x) {
    float r; asm("ex2.approx.ftz.f32 %0, %1;" : "=f"(r) : "f"(x)); return r;
}
__device__ __forceinline__ void mma16816(float c[4], const uint32_t a[4], const uint32_t b[2]) {
    asm volatile("mma.sync.aligned.m16n8k16.row.col.f32.f16.f16.f32 "
                 "{%0,%1,%2,%3}, {%4,%5,%6,%7}, {%8,%9}, {%0,%1,%2,%3};"
                 : "+f"(c[0]), "+f"(c[1]), "+f"(c[2]), "+f"(c[3])
                 : "r"(a[0]), "r"(a[1]), "r"(a[2]), "r"(a[3]), "r"(b[0]), "r"(b[1]));
}

// =================== GEMM (frozen at R12: co-limited local optimum) =========
#define RS2 144
#define TILE2 (128 * RS2)          // 18432 B
#define STAGE2 (2 * TILE2)         // 36864 B (A+B)
#define GSMEM (3 * STAGE2)         // 110592 B
#define NKT2 16                    // 1024 / 64

__device__ __forceinline__ void load_stage(uint32_t sbase,
                                           const __half* __restrict__ A,
                                           const __half* __restrict__ Bg,
                                           int kt, int tid) {
    const uint32_t sA = sbase, sB = sbase + TILE2;
    #pragma unroll
    for (int i = 0; i < 4; ++i) {
        int idx = tid + i * 256;
        int row = idx >> 3, c = idx & 7;
        const size_t go = (size_t)row * D_ + kt * 64 + c * 8;
        cpa16(sA + row * RS2 + c * 16, A + go);
        cpa16(sB + row * RS2 + c * 16, Bg + go);
    }
}

__device__ __forceinline__ void load_frag_a(uint32_t sA, int ks, int warp_m, int lane,
                                            int i, uint32_t a[4]) {
    int row = warp_m * 64 + i * 16 + (lane & 15);
    uint32_t addr = sA + row * RS2 + (ks * 16 + (lane >> 4) * 8) * 2;
    asm volatile("ldmatrix.sync.aligned.m8n8.x4.shared.b16 {%0,%1,%2,%3}, [%4];"
                 : "=r"(a[0]), "=r"(a[1]), "=r"(a[2]), "=r"(a[3]) : "r"(addr));
}

__device__ __forceinline__ void load_frag_b(uint32_t sB, int ks, int warp_n, int lane,
                                            int jj, uint32_t b0[2], uint32_t b1[2]) {
    int g = lane >> 3, lr = lane & 7;
    int n = warp_n * 32 + jj * 16 + (g >> 1) * 8 + lr;
    uint32_t addr = sB + n * RS2 + (ks * 16 + (g & 1) * 8) * 2;
    uint32_t r0, r1, r2, r3;
    asm volatile("ldmatrix.sync.aligned.m8n8.x4.shared.b16 {%0,%1,%2,%3}, [%4];"
                 : "=r"(r0), "=r"(r1), "=r"(r2), "=r"(r3) : "r"(addr));
    b0[0] = r0; b0[1] = r1;
    b1[0] = r2; b1[1] = r3;
}

__device__ __forceinline__ void gemm_main(uint32_t s, const __half* __restrict__ A,
                                          const __half* __restrict__ Bg,
                                          int tid, int warp_m, int warp_n, int lane,
                                          float c[4][4][4]) {
    load_stage(s + 0 * STAGE2, A, Bg, 0, tid); cpa_commit();
    load_stage(s + 1 * STAGE2, A, Bg, 1, tid); cpa_commit();

    uint32_t af[2][4][4], bf[2][4][2];

    #pragma unroll 1
    for (int kt = 0; kt < NKT2; ++kt) {
        if (kt < NKT2 - 1) asm volatile("cp.async.wait_group 1;" ::: "memory");
        else               asm volatile("cp.async.wait_group 0;" ::: "memory");
        __syncthreads();
        const uint32_t sA = s + (kt % 3) * STAGE2, sB = sA + TILE2;

        #pragma unroll
        for (int i = 0; i < 4; ++i) load_frag_a(sA, 0, warp_m, lane, i, af[0][i]);
        load_frag_b(sB, 0, warp_n, lane, 0, bf[0][0], bf[0][1]);
        load_frag_b(sB, 0, warp_n, lane, 1, bf[0][2], bf[0][3]);

        if (kt + 2 < NKT2) {
            load_stage(s + ((kt + 2) % 3) * STAGE2, A, Bg, kt + 2, tid);
            cpa_commit();
        }

        #pragma unroll
        for (int ks = 0; ks < 4; ++ks) {
            const int cur = ks & 1, nxt = cur ^ 1;
            const bool pf = (ks < 3);
            #pragma unroll
            for (int j = 0; j < 4; ++j) mma16816(c[0][j], af[cur][0], bf[cur][j]);
            if (pf) {
                load_frag_a(sA, ks + 1, warp_m, lane, 0, af[nxt][0]);
                load_frag_a(sA, ks + 1, warp_m, lane, 1, af[nxt][1]);
            }
            #pragma unroll
            for (int j = 0; j < 4; ++j) mma16816(c[1][j], af[cur][1], bf[cur][j]);
            if (pf) {
                load_frag_a(sA, ks + 1, warp_m, lane, 2, af[nxt][2]);
                load_frag_a(sA, ks + 1, warp_m, lane, 3, af[nxt][3]);
            }
            #pragma unroll
            for (int j = 0; j < 4; ++j) mma16816(c[2][j], af[cur][2], bf[cur][j]);
            if (pf) {
                load_frag_b(sB, ks + 1, warp_n, lane, 0, bf[nxt][0], bf[nxt][1]);
                load_frag_b(sB, ks + 1, warp_n, lane, 1, bf[nxt][2], bf[nxt][3]);
            }
            #pragma unroll
            for (int j = 0; j < 4; ++j) mma16816(c[3][j], af[cur][3], bf[cur][j]);
        }
    }
}

// ---------------------------------------------------------------------------
// QKV projection -> fp16 Q/K/V
// ---------------------------------------------------------------------------
__global__ __launch_bounds__(256, 2) void qkv_mma(
    const __half* __restrict__ Xh, const __half* __restrict__ Wt,
    const float* __restrict__ bq, const float* __restrict__ bk,
    const float* __restrict__ bv) {
    extern __shared__ __align__(16) char sm[];
    const uint32_t s = smem_u32(sm);
    const int tid = threadIdx.x, lane = tid & 31, wid = tid >> 5;
    const int warp_m = wid & 1, warp_n = wid >> 1;
    const int z = blockIdx.z, h0 = blockIdx.x * 2, m0 = blockIdx.y * 128;

    const __half* A  = Xh + (size_t)m0 * D_;
    const __half* Bg = Wt + ((size_t)(z * H_ + h0) * HD_) * D_;
    const float* bias = (z == 0) ? bq : (z == 1) ? bk : bv;
    __half* out       = (z == 0) ? g_qh : (z == 1) ? g_kh : g_vh;

    float c[4][4][4] = {};
    gemm_main(s, A, Bg, tid, warp_m, warp_n, lane, c);

    #pragma unroll
    for (int i = 0; i < 4; ++i) {
        #pragma unroll
        for (int j = 0; j < 4; ++j) {
            const int n = warp_n * 32 + j * 8 + (lane & 3) * 2;
            const int head = h0 + (n >> 6), e = n & 63;
            const float b0 = bias[head * HD_ + e], b1 = bias[head * HD_ + e + 1];
            #pragma unroll
            for (int half_ = 0; half_ < 2; ++half_) {
                const int m = m0 + warp_m * 64 + i * 16 + (lane >> 2) + half_ * 8;
                const int bb = m >> 11, sI = m & 2047;
                __half2 hv = __floats2half2_rn(c[i][j][half_ * 2 + 0] + b0,
                                               c[i][j][half_ * 2 + 1] + b1);
                *(__half2*)(out + (((size_t)(bb * H_ + head) * S_ + sI) * HD_ + e)) = hv;
            }
        }
    }
}

// ---------------------------------------------------------------------------
// Output projection: C = WVh * Woh^T + bo
// ---------------------------------------------------------------------------
__global__ __launch_bounds__(256, 2) void out_mma(
    const __half* __restrict__ WVh, const __half* __restrict__ Woh,
    const float* __restrict__ bo, float* __restrict__ outp) {
    extern __shared__ __align__(16) char sm[];
    const uint32_t s = smem_u32(sm);
    const int tid = threadIdx.x, lane = tid & 31, wid = tid >> 5;
    const int warp_m = wid & 1, warp_n = wid >> 1;
    const int n0 = blockIdx.x * 128, m0 = blockIdx.y * 128;

    const __half* A  = WVh + (size_t)m0 * D_;
    const __half* Bg = Woh + (size_t)n0 * D_;

    float c[4][4][4] = {};
    gemm_main(s, A, Bg, tid, warp_m, warp_n, lane, c);

    #pragma unroll
    for (int i = 0; i < 4; ++i) {
        #pragma unroll
        for (int j = 0; j < 4; ++j) {
            const int n = n0 + warp_n * 32 + j * 8 + (lane & 3) * 2;
            const float b0 = bo[n], b1 = bo[n + 1];
            #pragma unroll
            for (int half_ = 0; half_ < 2; ++half_) {
                const int m = m0 + warp_m * 64 + i * 16 + (lane >> 2) + half_ * 8;
                float2 v;
                v.x = c[i][j][half_ * 2 + 0] + b0;
                v.y = c[i][j][half_ * 2 + 1] + b1;
                *(float2*)(outp + (size_t)m * D_ + n) = v;
            }
        }
    }
}

// ===== attention: 128-key staging, two 64-key compute chunks per barrier =====
#define ARS 144
#define ATILE2 (128 * ARS)         // 18432 B (128 keys x 64 hd)
#define ASTG2 (2 * ATILE2)         // 36864 B (K+V)
#define ASMEM (3 * ASTG2)          // 110592 B

__global__ __launch_bounds__(256, 2) void attn_mma() {
    extern __shared__ __align__(16) char sm[];
    const uint32_t s = smem_u32(sm);
    const int tid = threadIdx.x, lane = tid & 31, w = tid >> 5;
    const int bh = blockIdx.y;
    const int q0 = (gridDim.x - 1 - blockIdx.x) * 128;   // heavy tiles first

    const __half* __restrict__ Qb = g_qh + (size_t)bh * S_ * HD_;
    const __half* __restrict__ Kb = g_kh + (size_t)bh * S_ * HD_;
    const __half* __restrict__ Vb = g_vh + (size_t)bh * S_ * HD_;

    const int r0 = q0 + w * 16 + (lane >> 2);
    const int cq = lane & 3;
    const float SC = 0.18033688f;                 // 0.125 * log2(e)
    uint32_t qf[4][4];
    {
        const __half2 sc2 = __floats2half2_rn(SC, SC);
        const __half2* Qr0 = (const __half2*)(Qb + (size_t)r0 * HD_);
        const __half2* Qr1 = (const __half2*)(Qb + (size_t)(r0 + 8) * HD_);
        #pragma unroll
        for (int t = 0; t < 4; ++t) {
            __half2 v0 = __hmul2(Qr0[t * 8 + cq], sc2);
            __half2 v1 = __hmul2(Qr1[t * 8 + cq], sc2);
            __half2 v2 = __hmul2(Qr0[t * 8 + 4 + cq], sc2);
            __half2 v3 = __hmul2(Qr1[t * 8 + 4 + cq], sc2);
            qf[t][0] = *(const uint32_t*)&v0;
            qf[t][1] = *(const uint32_t*)&v1;
            qf[t][2] = *(const uint32_t*)&v2;
            qf[t][3] = *(const uint32_t*)&v3;
        }
    }

    float o[8][4];
    #pragma unroll
    for (int j = 0; j < 8; ++j)
        #pragma unroll
        for (int x = 0; x < 4; ++x) o[j][x] = 0.f;
    float m0 = -INFINITY, m1 = -INFINITY, l0 = 0.f, l1 = 0.f;

    const int NT = (q0 + 128) / 128;              // 128-key tiles

    // K rows [kt*128, kt*128+128) at stage base; V same at +ATILE2
    auto load_tile = [&](int kt, int stg) {
        const uint32_t base = s + stg * ASTG2;
        #pragma unroll
        for (int i = 0; i < 4; ++i) {
            int idx = tid + i * 256;              // 0..1023
            int row = idx >> 3, c = idx & 7;      // 128 rows x 8 chunks
            const size_t go = (size_t)(kt * 128 + row) * HD_ + c * 8;
            cpa16(base + row * ARS + c * 16, Kb + go);
            cpa16(base + ATILE2 + row * ARS + c * 16, Vb + go);
        }
    };

    load_tile(0, 0); cpa_commit();
    if (NT > 1) { load_tile(1, 1); cpa_commit(); }

    const int g = lane >> 3, lr = lane & 7;
    const uint32_t ONES2 = 0x3C003C00u;
    uint32_t onesb[2] = {ONES2, ONES2};

    #pragma unroll 1
    for (int kt = 0; kt < NT; ++kt) {
        if (kt < NT - 1) asm volatile("cp.async.wait_group 1;" ::: "memory");
        else             asm volatile("cp.async.wait_group 0;" ::: "memory");
        __syncthreads();
        if (kt + 2 < NT) { load_tile(kt + 2, (kt + 2) % 3); cpa_commit(); }

        const uint32_t sKbase = s + (kt % 3) * ASTG2;

        #pragma unroll 1
        for (int half64 = 0; half64 < 2; ++half64) {
            const int k0 = kt * 128 + half64 * 64;
            const uint32_t sK = sKbase + half64 * 64 * ARS;
            const uint32_t sV = sKbase + ATILE2 + half64 * 64 * ARS;

            // ---- S = (Q*sc) K^T ----
            float sa[8][4];
            #pragma unroll
            for (int j = 0; j < 8; ++j)
                #pragma unroll
                for (int x = 0; x < 4; ++x) sa[j][x] = 0.f;
            #pragma unroll
            for (int t = 0; t < 4; ++t) {
                uint32_t kb[8][2];
                #pragma unroll
                for (int jp = 0; jp < 4; ++jp) {
                    const int n = jp * 16 + (g >> 1) * 8 + lr;
                    uint32_t addr = sK + n * ARS + t * 32 + (g & 1) * 16;
                    uint32_t r0_, r1_, r2_, r3_;
                    asm volatile("ldmatrix.sync.aligned.m8n8.x4.shared.b16 {%0,%1,%2,%3}, [%4];"
                                 : "=r"(r0_), "=r"(r1_), "=r"(r2_), "=r"(r3_) : "r"(addr));
                    kb[jp * 2][0] = r0_; kb[jp * 2][1] = r1_;
                    kb[jp * 2 + 1][0] = r2_; kb[jp * 2 + 1][1] = r3_;
                }
                #pragma unroll
                for (int j = 0; j < 8; ++j)
                    mma16816(sa[j], qf[t], kb[j]);
            }

            // ---- mask + running-max ----
            const bool needmask = (k0 + 63 > r0);
            float tm0 = -INFINITY, tm1 = -INFINITY;
            #pragma unroll
            for (int j = 0; j < 8; ++j) {
                if (needmask) {
                    const int col = k0 + j * 8 + (lane & 3) * 2;
                    if (col > r0)         sa[j][0] = -INFINITY;
                    if (col + 1 > r0)     sa[j][1] = -INFINITY;
                    if (col > r0 + 8)     sa[j][2] = -INFINITY;
                    if (col + 1 > r0 + 8) sa[j][3] = -INFINITY;
                }
                tm0 = fmaxf(tm0, fmaxf(sa[j][0], sa[j][1]));
                tm1 = fmaxf(tm1, fmaxf(sa[j][2], sa[j][3]));
            }
            tm0 = fmaxf(tm0, __shfl_xor_sync(0xffffffffu, tm0, 1));
            tm0 = fmaxf(tm0, __shfl_xor_sync(0xffffffffu, tm0, 2));
            tm1 = fmaxf(tm1, __shfl_xor_sync(0xffffffffu, tm1, 1));
            tm1 = fmaxf(tm1, __shfl_xor_sync(0xffffffffu, tm1, 2));

            const float mn0 = fmaxf(m0, tm0), mn1 = fmaxf(m1, tm1);
            const float c0 = ex2(m0 - mn0), c1 = ex2(m1 - mn1);
            m0 = mn0; m1 = mn1;

            // ---- P = exp2(S - m) in fp16x2 ----
            uint32_t pa[4][4];
            #pragma unroll
            for (int j = 0; j < 8; ++j) {
                const float a0 = sa[j][0] - mn0, a1 = sa[j][1] - mn0;
                const float a2 = sa[j][2] - mn1, a3 = sa[j][3] - mn1;
                uint32_t h01, h23;
                asm("cvt.rn.f16x2.f32 %0, %1, %2;" : "=r"(h01) : "f"(a1), "f"(a0));
                asm("cvt.rn.f16x2.f32 %0, %1, %2;" : "=r"(h23) : "f"(a3), "f"(a2));
                asm("ex2.approx.f16x2 %0, %1;" : "=r"(h01) : "r"(h01));
                asm("ex2.approx.f16x2 %0, %1;" : "=r"(h23) : "r"(h23));
                const int t = j >> 1;
                if ((j & 1) == 0) { pa[t][0] = h01; pa[t][1] = h23; }
                else              { pa[t][2] = h01; pa[t][3] = h23; }
            }

            // ---- rescale O ----
            #pragma unroll
            for (int j = 0; j < 8; ++j) {
                o[j][0] *= c0; o[j][1] *= c0;
                o[j][2] *= c1; o[j][3] *= c1;
            }

            // ---- O += P V, row sums via MMA ----
            float ls[4] = {0.f, 0.f, 0.f, 0.f};
            #pragma unroll
            for (int t = 0; t < 4; ++t) {
                uint32_t vb[8][2];
                #pragma unroll
                for (int jp = 0; jp < 4; ++jp) {
                    const int row = t * 16 + (g & 1) * 8 + lr;
                    uint32_t addr = sV + row * ARS + jp * 32 + (g >> 1) * 16;
                    uint32_t r0_, r1_, r2_, r3_;
                    asm volatile("ldmatrix.sync.aligned.m8n8.x4.trans.shared.b16 {%0,%1,%2,%3}, [%4];"
                                 : "=r"(r0_), "=r"(r1_), "=r"(r2_), "=r"(r3_) : "r"(addr));
                    vb[jp * 2][0] = r0_; vb[jp * 2][1] = r1_;
                    vb[jp * 2 + 1][0] = r2_; vb[jp * 2 + 1][1] = r3_;
                }
                mma16816(ls, pa[t], onesb);
                #pragma unroll
                for (int j = 0; j < 8; ++j)
                    mma16816(o[j], pa[t], vb[j]);
            }

            l0 = l0 * c0 + ls[0];
            l1 = l1 * c1 + ls[2];
        }
    }

    // ---- epilogue ----
    const float i0 = 1.f / l0, i1 = 1.f / l1;
    const int b = bh >> 4, h = bh & 15;
    __half* out0 = g_wvh + ((size_t)(b * S_) + r0) * D_ + h * HD_ + (lane & 3) * 2;
    __half* out1 = g_wvh + ((size_t)(b * S_) + r0 + 8) * D_ + h * HD_ + (lane & 3) * 2;
    #pragma unroll
    for (int j = 0; j < 8; ++j) {
        *(__half2*)(out0 + j * 8) = __floats2half2_rn(o[j][0] * i0, o[j][1] * i0);
        *(__half2*)(out1 + j * 8) = __floats2half2_rn(o[j][2] * i1, o[j][3] * i1);
    }
}

// ---------------------------------------------------------------------------
// fused prep: cvt X (blocks 0..4095), cvt Wo (4096..4607), wtrans (4608..7679)
// converts use 512 threads x 4 elems; wtrans keeps 256-thread shape (pads to 512)
// ---------------------------------------------------------------------------
#define NB_X  4096
#define NB_WO 512
#define NB_WT 3072

__global__ __launch_bounds__(512) void prep(
    const float* __restrict__ X,  const float* __restrict__ Wo,
    const float* __restrict__ Wq, const float* __restrict__ Wk,
    const float* __restrict__ Wv) {
    __shared__ float t[32][33];
    const int b = blockIdx.x, tid = threadIdx.x;

    if (b < NB_X) {
        const int i = (b * 512 + tid) * 4;
        float4 v = *(const float4*)(X + i);
        __half2* o = (__half2*)(g_xh + i);
        o[0] = __floats2half2_rn(v.x, v.y);
        o[1] = __floats2half2_rn(v.z, v.w);
    } else if (b < NB_X + NB_WO) {
        const int i = ((b - NB_X) * 512 + tid) * 4;
        float4 v = *(const float4*)(Wo + i);
        __half2* o = (__half2*)(g_woh + i);
        o[0] = __floats2half2_rn(v.x, v.y);
        o[1] = __floats2half2_rn(v.z, v.w);
    } else {
        if (tid >= 256) return;
        const int id = b - NB_X - NB_WO;
        const int bx = id & 1, by = (id >> 1) & 31, bz = id >> 6;
        const int z = bz >> 4, h = bz & 15;
        const float* W = ((z == 0) ? Wq : (z == 1) ? Wk : Wv) + (size_t)h * D_ * HD_;
        __half* out = g_wt + (size_t)bz * HD_ * D_;
        const int n0 = bx * 32, k0 = by * 32;
        const int tx = tid & 31, ty = tid >> 5;
        #pragma unroll
        for (int i = 0; i < 32; i += 8)
            t[ty + i][tx] = W[(size_t)(k0 + ty + i) * HD_ + n0 + tx];
        __syncthreads();
        #pragma unroll
        for (int i = 0; i < 32; i += 8)
            out[(size_t)(n0 + ty + i) * D_ + k0 + tx] = __float2half_rn(t[tx][ty + i]);
    }
}

// ---------------------------------------------------------------------------
extern "C" void kernel_launch(void* const* d_in, const int* in_sizes, int n_in,
                              void* d_out, int out_size) {
    const float* X  = (const float*)d_in[0];
    const float* Wq = (const float*)d_in[1];
    const float* bq = (const float*)d_in[2];
    const float* Wk = (const float*)d_in[3];
    const float* bk = (const float*)d_in[4];
    const float* Wv = (const float*)d_in[5];
    const float* bv = (const float*)d_in[6];
    const float* Wo = (const float*)d_in[7];
    const float* bo = (const float*)d_in[8];
    float* out = (float*)d_out;

    cudaFuncSetAttribute(qkv_mma, cudaFuncAttributeMaxDynamicSharedMemorySize, GSMEM);
    cudaFuncSetAttribute(out_mma, cudaFuncAttributeMaxDynamicSharedMemorySize, GSMEM);
    cudaFuncSetAttribute(attn_mma, cudaFuncAttributeMaxDynamicSharedMemorySize, ASMEM);

    __half* xh  = nullptr; cudaGetSymbolAddress((void**)&xh,  g_xh);
    __half* wvh = nullptr; cudaGetSymbolAddress((void**)&wvh, g_wvh);
    __half* wt  = nullptr; cudaGetSymbolAddress((void**)&wt,  g_wt);
    __half* woh = nullptr; cudaGetSymbolAddress((void**)&woh, g_woh);

    prep<<<NB_X + NB_WO + NB_WT, 512>>>(X, Wo, Wq, Wk, Wv);
    qkv_mma<<<dim3(H_ / 2, M_ / 128, 3), 256, GSMEM>>>(xh, wt, bq, bk, bv);
    attn_mma<<<dim3(S_ / 128, B_ * H_), 256, ASMEM>>>();
    out_mma<<<dim3(D_ / 128, M_ / 128), 256, GSMEM>>>(wvh, woh, bo, out);
}